// round 12
// baseline (speedup 1.0000x reference)
#include <cuda_runtime.h>
#include <cuda_fp16.h>
#include <cstdint>

// ---------------------------------------------------------------------------
// BaseLoftqLinear, fused persistent kernel:
//   W' = dequant4(q, s) + 2.0 * (B @ A);  out = x @ W'^T + bias
// 148 co-resident CTAs. Phase A: all CTAs prep X + W(nt0-7). Phase B: CTAs
// 128-147 prep W(nt8-15) WHILE CTAs 0-127 run round-1 GEMM tiles (nt0-7);
// round-2 tiles (nt8-15) spin on completion flags (producers are straight-
// line code in resident CTAs -> no deadlock). fp16 mma.sync m16n8k16 fp32-acc.
// ---------------------------------------------------------------------------

#define OUT_F 4096
#define IN_F  4096
#define M_TOK 2048
#define R_LORA 16

// packed 16B-chunk layouts (chunk stored at ch ^ (row&7)):
//   X: [mt(16)][kt(64)][row(128)][chunk(8)]
//   W: [nt(16)][kt(64)][row(256)][chunk(8)]
__device__ uint4 g_Xp[(size_t)M_TOK * IN_F / 8];   // 16 MB
__device__ uint4 g_Wp[(size_t)OUT_F * IN_F / 8];   // 32 MB
__device__ int   g_xdone[16];                      // X tiles done per mt (goal 64)
__device__ int   g_wdone[16];                      // W tiles done per nt (goal 64)

#define NTHREADS 512
#define STAGES 4
#define STAGE_CHUNKS 3072                           // A 1024 + B 2048 (16B each)
#define SMEM_BYTES (STAGES * STAGE_CHUNKS * 16)     // 196608
#define NITER 64                                    // IN_F / 64

__device__ __forceinline__ uint32_t smem_u32(const void* p) {
    uint32_t a;
    asm("{ .reg .u64 t; cvta.to.shared.u64 t, %1; cvt.u32.u64 %0, t; }"
        : "=r"(a) : "l"(p));
    return a;
}

__device__ __forceinline__ uint32_t h2_u32(__half2 h) {
    union { __half2 h; uint32_t u; } cvt;
    cvt.h = h;
    return cvt.u;
}

__device__ __forceinline__ void cp_async16(uint32_t dst, const void* src) {
    asm volatile("cp.async.cg.shared.global [%0], [%1], 16;"
                 :: "r"(dst), "l"(src) : "memory");
}

__device__ __forceinline__ void ldmx4(uint32_t* r, uint32_t addr) {
    asm volatile("ldmatrix.sync.aligned.m8n8.x4.shared.b16 {%0,%1,%2,%3}, [%4];"
                 : "=r"(r[0]), "=r"(r[1]), "=r"(r[2]), "=r"(r[3]) : "r"(addr));
}

__device__ __forceinline__ void mma_f16(float* d, const uint32_t* a,
                                        uint32_t b0, uint32_t b1) {
    asm volatile(
        "mma.sync.aligned.m16n8k16.row.col.f32.f16.f16.f32 "
        "{%0,%1,%2,%3}, {%4,%5,%6,%7}, {%8,%9}, {%0,%1,%2,%3};"
        : "+f"(d[0]), "+f"(d[1]), "+f"(d[2]), "+f"(d[3])
        : "r"(a[0]), "r"(a[1]), "r"(a[2]), "r"(a[3]), "r"(b0), "r"(b1));
}

// ---------------------------------------------------------------------------
// Prep: one X tile (128 rows x 64 cols), 512 threads
// ---------------------------------------------------------------------------
__device__ __noinline__ void prep_X(const float* __restrict__ x, int bb)
{
    const int t  = threadIdx.x;
    const int mt = bb >> 6;
    const int kt = bb & 63;
    uint4* dst = g_Xp + (size_t)bb * 1024;
#pragma unroll
    for (int i = 0; i < 2; i++) {
        int c   = t + i * 512;             // chunk id 0..1023
        int row = c >> 3;
        int ch  = c & 7;
        const float* src = x + ((size_t)(mt * 128 + row)) * IN_F + kt * 64 + ch * 8;
        float4 v0 = *(const float4*)(src);
        float4 v1 = *(const float4*)(src + 4);
        uint4 o;
        o.x = h2_u32(__floats2half2_rn(v0.x, v0.y));
        o.y = h2_u32(__floats2half2_rn(v0.z, v0.w));
        o.z = h2_u32(__floats2half2_rn(v1.x, v1.y));
        o.w = h2_u32(__floats2half2_rn(v1.z, v1.w));
        dst[row * 8 + (ch ^ (row & 7))] = o;
    }
}

// ---------------------------------------------------------------------------
// Prep: one W tile (256 rows x 64 cols), 512 threads (2 per row)
// ---------------------------------------------------------------------------
__device__ __noinline__ void prep_W(char* smem_raw,
                                    const int* __restrict__ qweight,
                                    const float* __restrict__ scales,
                                    const float* __restrict__ lora_A,
                                    const float* __restrict__ lora_B,
                                    int b)
{
    __half2 (*sA2)[32] = (__half2(*)[32])smem_raw;   // 16x32 half2 = 2 KB
    const int t  = threadIdx.x;
    const int nt = b >> 6;
    const int kt = b & 63;

    __syncthreads();                       // prior smem users done
    if (t < 256) {
        int r  = t >> 4;
        int c4 = t & 15;
        float4 a = *(const float4*)(lora_A + (size_t)r * IN_F + kt * 64 + c4 * 4);
        sA2[r][c4 * 2]     = __floats2half2_rn(a.x, a.y);
        sA2[r][c4 * 2 + 1] = __floats2half2_rn(a.z, a.w);
    }
    __syncthreads();

    const int row   = t >> 1;              // 0..255
    const int hlf   = t & 1;               // chunks [hlf*4, hlf*4+4)
    const int row_g = nt * 256 + row;

    __half2 Bh[R_LORA];
    {
        float4 b0 = *(const float4*)(lora_B + (size_t)row_g * R_LORA + 0);
        float4 b1 = *(const float4*)(lora_B + (size_t)row_g * R_LORA + 4);
        float4 b2 = *(const float4*)(lora_B + (size_t)row_g * R_LORA + 8);
        float4 b3 = *(const float4*)(lora_B + (size_t)row_g * R_LORA + 12);
        Bh[0]  = __float2half2_rn(2.0f * b0.x);
        Bh[1]  = __float2half2_rn(2.0f * b0.y);
        Bh[2]  = __float2half2_rn(2.0f * b0.z);
        Bh[3]  = __float2half2_rn(2.0f * b0.w);
        Bh[4]  = __float2half2_rn(2.0f * b1.x);
        Bh[5]  = __float2half2_rn(2.0f * b1.y);
        Bh[6]  = __float2half2_rn(2.0f * b1.z);
        Bh[7]  = __float2half2_rn(2.0f * b1.w);
        Bh[8]  = __float2half2_rn(2.0f * b2.x);
        Bh[9]  = __float2half2_rn(2.0f * b2.y);
        Bh[10] = __float2half2_rn(2.0f * b2.z);
        Bh[11] = __float2half2_rn(2.0f * b2.w);
        Bh[12] = __float2half2_rn(2.0f * b3.x);
        Bh[13] = __float2half2_rn(2.0f * b3.y);
        Bh[14] = __float2half2_rn(2.0f * b3.z);
        Bh[15] = __float2half2_rn(2.0f * b3.w);
    }
    const float s = scales[(size_t)row_g * 64 + kt];
    const float step = 2.0f / 15.0f;
    const uint4* qv = (const uint4*)qweight;
    uint4* dst = g_Wp + (size_t)b * 2048 + row * 8;

#pragma unroll
    for (int j = 0; j < 4; j++) {
        const int ch = hlf * 4 + j;
        __half2 l2[4];
        l2[0] = __float2half2_rn(0.0f);
        l2[1] = l2[0]; l2[2] = l2[0]; l2[3] = l2[0];
#pragma unroll
        for (int r = 0; r < R_LORA; r++) {
            uint4 av = *(const uint4*)&sA2[r][ch * 4];
            l2[0] = __hfma2(Bh[r], *(__half2*)&av.x, l2[0]);
            l2[1] = __hfma2(Bh[r], *(__half2*)&av.y, l2[1]);
            l2[2] = __hfma2(Bh[r], *(__half2*)&av.z, l2[2]);
            l2[3] = __hfma2(Bh[r], *(__half2*)&av.w, l2[3]);
        }
        float2 lf0 = __half22float2(l2[0]);
        float2 lf1 = __half22float2(l2[1]);
        float2 lf2 = __half22float2(l2[2]);
        float2 lf3 = __half22float2(l2[3]);

        uint4 q = qv[(size_t)row_g * 512 + kt * 8 + ch];
        float w[8];
        w[0] = fmaf(fmaf((float)(q.x & 15),        step, -1.0f), s, lf0.x);
        w[1] = fmaf(fmaf((float)((q.x >> 4) & 15), step, -1.0f), s, lf0.y);
        w[2] = fmaf(fmaf((float)(q.y & 15),        step, -1.0f), s, lf1.x);
        w[3] = fmaf(fmaf((float)((q.y >> 4) & 15), step, -1.0f), s, lf1.y);
        w[4] = fmaf(fmaf((float)(q.z & 15),        step, -1.0f), s, lf2.x);
        w[5] = fmaf(fmaf((float)((q.z >> 4) & 15), step, -1.0f), s, lf2.y);
        w[6] = fmaf(fmaf((float)(q.w & 15),        step, -1.0f), s, lf3.x);
        w[7] = fmaf(fmaf((float)((q.w >> 4) & 15), step, -1.0f), s, lf3.y);

        uint4 o;
        o.x = h2_u32(__floats2half2_rn(w[0], w[1]));
        o.y = h2_u32(__floats2half2_rn(w[2], w[3]));
        o.z = h2_u32(__floats2half2_rn(w[4], w[5]));
        o.w = h2_u32(__floats2half2_rn(w[6], w[7]));
        dst[ch ^ (row & 7)] = o;
    }
}

// ---------------------------------------------------------------------------
// One GEMM tile: CTA tile 128x256, BK=64, 4-stage cp.async, 16 warps (2Mx8N)
// ---------------------------------------------------------------------------
__device__ __noinline__ void run_tile(uint4* smem,
                                      const float* __restrict__ bias,
                                      float* __restrict__ out,
                                      int mt, int nt)
{
    // wait for dependencies (producers are straight-line code in resident CTAs)
    if (threadIdx.x == 0) {
        volatile int* px = (volatile int*)(g_xdone + mt);
        volatile int* pw = (volatile int*)(g_wdone + nt);
        while (*px < 64 || *pw < 64) {}
        __threadfence();
    }
    __syncthreads();   // also separates previous tile's smem use from prologue

    const uint32_t sbase = smem_u32(smem);
    const int t    = threadIdx.x;
    const int lane = t & 31;
    const int wid  = t >> 5;
    const int g4   = lane >> 2;
    const int l4   = lane & 3;
    const int wm   = wid & 1;
    const int wn   = wid >> 1;

    const int ar = lane & 7;
    const int ag = lane >> 3;
    const int rg = ag & 1;
    const int cg = ag >> 1;
    const uint32_t arow_off = (uint32_t)(wm * 64 + rg * 8 + ar) * 128u;
    const uint32_t brow_off = (uint32_t)(wn * 32 + rg * 8 + ar) * 128u;
    uint32_t sw[4];
#pragma unroll
    for (int ks = 0; ks < 4; ks++)
        sw[ks] = (uint32_t)(((ks * 2 + cg) ^ ar) * 16);

    const uint4* srcA0 = g_Xp + (size_t)mt * 64 * 1024;
    const uint4* srcB0 = g_Wp + (size_t)nt * 64 * 2048;

    float acc[4][4][4];
#pragma unroll
    for (int mf = 0; mf < 4; mf++)
#pragma unroll
        for (int nf = 0; nf < 4; nf++)
#pragma unroll
            for (int j = 0; j < 4; j++) acc[mf][nf][j] = 0.0f;

    auto load_stage = [&](int it, int s) {
        uint32_t d = sbase + (uint32_t)(s * STAGE_CHUNKS * 16);
        const uint4* sa = srcA0 + (size_t)it * 1024;
        const uint4* sb = srcB0 + (size_t)it * 2048;
#pragma unroll
        for (int i = 0; i < 2; i++)
            cp_async16(d + (t + i * NTHREADS) * 16, sa + t + i * NTHREADS);
        d += 1024 * 16;
#pragma unroll
        for (int i = 0; i < 4; i++)
            cp_async16(d + (t + i * NTHREADS) * 16, sb + t + i * NTHREADS);
        asm volatile("cp.async.commit_group;" ::: "memory");
    };

    load_stage(0, 0);
    load_stage(1, 1);
    load_stage(2, 2);

#pragma unroll 1
    for (int it = 0; it < NITER; ++it) {
        if (it < NITER - 2)
            asm volatile("cp.async.wait_group 2;" ::: "memory");
        else if (it == NITER - 2)
            asm volatile("cp.async.wait_group 1;" ::: "memory");
        else
            asm volatile("cp.async.wait_group 0;" ::: "memory");
        __syncthreads();

        if (it + 3 < NITER) load_stage(it + 3, (it + 3) % STAGES);

        const uint32_t aS = sbase + (uint32_t)((it % STAGES) * STAGE_CHUNKS * 16);
        const uint32_t bS = aS + 1024 * 16;

#pragma unroll
        for (int ks = 0; ks < 4; ks++) {
            uint32_t a[4][4], b[2][4];
#pragma unroll
            for (int mf = 0; mf < 4; mf++)
                ldmx4(a[mf], aS + arow_off + mf * 2048 + sw[ks]);
#pragma unroll
            for (int p = 0; p < 2; p++)
                ldmx4(b[p], bS + brow_off + p * 2048 + sw[ks]);

#pragma unroll
            for (int mf = 0; mf < 4; mf++)
#pragma unroll
                for (int p = 0; p < 2; p++) {
                    mma_f16(acc[mf][2 * p],     a[mf], b[p][0], b[p][2]);
                    mma_f16(acc[mf][2 * p + 1], a[mf], b[p][1], b[p][3]);
                }
        }
    }

    const int m0 = mt * 128 + wm * 64;
    const int n0 = nt * 256 + wn * 32;

    float2 bb[4];
#pragma unroll
    for (int nf = 0; nf < 4; nf++)
        bb[nf] = *(const float2*)(bias + n0 + nf * 8 + l4 * 2);

#pragma unroll
    for (int mf = 0; mf < 4; mf++) {
        const int m = m0 + mf * 16 + g4;
        float* r0 = out + (size_t)m * OUT_F;
        float* r1 = out + (size_t)(m + 8) * OUT_F;
#pragma unroll
        for (int nf = 0; nf < 4; nf++) {
            const int n = n0 + nf * 8 + l4 * 2;
            float2 v0, v1;
            v0.x = acc[mf][nf][0] + bb[nf].x;
            v0.y = acc[mf][nf][1] + bb[nf].y;
            v1.x = acc[mf][nf][2] + bb[nf].x;
            v1.y = acc[mf][nf][3] + bb[nf].y;
            *(float2*)(r0 + n) = v0;
            *(float2*)(r1 + n) = v1;
        }
    }
    __syncthreads();   // all warps done with smem before next tile's prologue
}

// ---------------------------------------------------------------------------
// Fused persistent kernel: 148 CTAs (all co-resident), 512 threads.
// ---------------------------------------------------------------------------
__global__ void zero_kernel()
{
    int t = threadIdx.x;
    if (t < 16) { g_xdone[t] = 0; g_wdone[t] = 0; }
}

__global__ __launch_bounds__(NTHREADS, 1)
void fused_kernel(const float* __restrict__ x,
                  const int* __restrict__ qweight,
                  const float* __restrict__ scales,
                  const float* __restrict__ lora_A,
                  const float* __restrict__ lora_B,
                  const float* __restrict__ bias,
                  float* __restrict__ out)
{
    extern __shared__ uint4 smem[];
    const int c = blockIdx.x;          // 0..147

    // ---- Phase A: X (1024 items) + W nt0-7 (512 items), all CTAs ----
    for (int ia = c; ia < 1536; ia += 148) {
        if (ia < 1024) {
            prep_X(x, ia);
            __threadfence();
            __syncthreads();
            if (threadIdx.x == 0) atomicAdd(&g_xdone[ia >> 6], 1);
        } else {
            int b = ia - 1024;         // 0..511 -> nt 0..7
            prep_W((char*)smem, qweight, scales, lora_A, lora_B, b);
            __threadfence();
            __syncthreads();
            if (threadIdx.x == 0) atomicAdd(&g_wdone[b >> 6], 1);
        }
    }

    // ---- Phase B: W nt8-15 (512 items), CTAs 128..147 only ----
    if (c >= 128) {
        for (int b = 512 + (c - 128); b < 1024; b += 20) {
            prep_W((char*)smem, qweight, scales, lora_A, lora_B, b);
            __threadfence();
            __syncthreads();
            if (threadIdx.x == 0) atomicAdd(&g_wdone[b >> 6], 1);
        }
    }

    // ---- GEMM: CTAs 0..127, two tiles each ----
    if (c < 128) {
        const int mt = c & 15;
        const int nt = c >> 4;         // 0..7
        run_tile(smem, bias, out, mt, nt);
        run_tile(smem, bias, out, mt, nt + 8);
    }
}

// ---------------------------------------------------------------------------
// Launch: x, qweight, scales, bias, lora_A, lora_B
// ---------------------------------------------------------------------------
extern "C" void kernel_launch(void* const* d_in, const int* in_sizes, int n_in,
                              void* d_out, int out_size)
{
    const float* x      = (const float*)d_in[0];
    const int*   qw     = (const int*)  d_in[1];
    const float* scales = (const float*)d_in[2];
    const float* bias   = (const float*)d_in[3];
    const float* lora_A = (const float*)d_in[4];
    const float* lora_B = (const float*)d_in[5];
    float*       out    = (float*)d_out;
    (void)in_sizes; (void)n_in; (void)out_size;

    cudaFuncSetAttribute(fused_kernel,
                         cudaFuncAttributeMaxDynamicSharedMemorySize, SMEM_BYTES);

    zero_kernel<<<1, 32>>>();
    fused_kernel<<<148, NTHREADS, SMEM_BYTES>>>(x, qw, scales, lora_A, lora_B,
                                                bias, out);
}

// round 13
// speedup vs baseline: 1.0099x; 1.0099x over previous
#include <cuda_runtime.h>
#include <cuda_fp16.h>
#include <cstdint>

// ---------------------------------------------------------------------------
// BaseLoftqLinear:
//   W' = dequant4(q, s) + 2.0 * (B @ A);   out = x @ W'^T + bias
// fp16 mma.sync.m16n8k16 (fp32 accum), pre-packed/pre-swizzled operands.
// Wave-tail fix: 148 full tiles (one exact wave) + the remaining 108 tiles
// as 432 K-quarter tiles (atomicAdd onto bias-pre-initialized out).
// ---------------------------------------------------------------------------

#define OUT_F 4096
#define IN_F  4096
#define M_TOK 2048
#define R_LORA 16

// packed 16B-chunk layouts (chunk stored at ch ^ (row&7)):
//   X: [mt(16)][kt(64)][row(128)][chunk(8)]
//   W: [nt(16)][kt(64)][row(256)][chunk(8)]
__device__ uint4 g_Xp[(size_t)M_TOK * IN_F / 8];   // 16 MB
__device__ uint4 g_Wp[(size_t)OUT_F * IN_F / 8];   // 32 MB

#define NTHREADS 512
#define STAGES 4
#define STAGE_CHUNKS 3072                           // A 1024 + B 2048 (16B each)
#define SMEM_BYTES (STAGES * STAGE_CHUNKS * 16)     // 196608

__device__ __forceinline__ uint32_t smem_u32(const void* p) {
    uint32_t a;
    asm("{ .reg .u64 t; cvta.to.shared.u64 t, %1; cvt.u32.u64 %0, t; }"
        : "=r"(a) : "l"(p));
    return a;
}

__device__ __forceinline__ uint32_t h2_u32(__half2 h) {
    union { __half2 h; uint32_t u; } cvt;
    cvt.h = h;
    return cvt.u;
}

__device__ __forceinline__ void cp_async16(uint32_t dst, const void* src) {
    asm volatile("cp.async.cg.shared.global [%0], [%1], 16;"
                 :: "r"(dst), "l"(src) : "memory");
}

__device__ __forceinline__ void ldmx4(uint32_t* r, uint32_t addr) {
    asm volatile("ldmatrix.sync.aligned.m8n8.x4.shared.b16 {%0,%1,%2,%3}, [%4];"
                 : "=r"(r[0]), "=r"(r[1]), "=r"(r[2]), "=r"(r[3]) : "r"(addr));
}

__device__ __forceinline__ void mma_f16(float* d, const uint32_t* a,
                                        uint32_t b0, uint32_t b1) {
    asm volatile(
        "mma.sync.aligned.m16n8k16.row.col.f32.f16.f16.f32 "
        "{%0,%1,%2,%3}, {%4,%5,%6,%7}, {%8,%9}, {%0,%1,%2,%3};"
        : "+f"(d[0]), "+f"(d[1]), "+f"(d[2]), "+f"(d[3])
        : "r"(a[0]), "r"(a[1]), "r"(a[2]), "r"(a[3]), "r"(b0), "r"(b1));
}

// ---------------------------------------------------------------------------
// Prep kernel: blocks 0..1023 = W tiles, 1024..2047 = X tiles,
//              2048..2303 = out := bias broadcast (for the atomic quarters).
// ---------------------------------------------------------------------------
__global__ __launch_bounds__(256)
void prep_kernel(const float* __restrict__ x,
                 const int* __restrict__ qweight,
                 const float* __restrict__ scales,
                 const float* __restrict__ lora_A,   // [R, IN_F]
                 const float* __restrict__ lora_B,   // [OUT_F, R]
                 const float* __restrict__ bias,
                 float* __restrict__ out)
{
    const int t = threadIdx.x;
    const int b = blockIdx.x;

    if (b < 1024) {
        // ---- W tile: nt = b>>6, kt = b&63; 256 rows x 64 cols ----
        __shared__ __half2 sA2[R_LORA][32];
        const int nt = b >> 6;
        const int kt = b & 63;

        {
            int r  = t >> 4;
            int c4 = t & 15;
            float4 a = *(const float4*)(lora_A + (size_t)r * IN_F + kt * 64 + c4 * 4);
            sA2[r][c4 * 2]     = __floats2half2_rn(a.x, a.y);
            sA2[r][c4 * 2 + 1] = __floats2half2_rn(a.z, a.w);
        }
        __syncthreads();

        const int row_g = nt * 256 + t;
        __half2 Bh[R_LORA];
        {
            float4 b0 = *(const float4*)(lora_B + (size_t)row_g * R_LORA + 0);
            float4 b1 = *(const float4*)(lora_B + (size_t)row_g * R_LORA + 4);
            float4 b2 = *(const float4*)(lora_B + (size_t)row_g * R_LORA + 8);
            float4 b3 = *(const float4*)(lora_B + (size_t)row_g * R_LORA + 12);
            Bh[0]  = __float2half2_rn(2.0f * b0.x);
            Bh[1]  = __float2half2_rn(2.0f * b0.y);
            Bh[2]  = __float2half2_rn(2.0f * b0.z);
            Bh[3]  = __float2half2_rn(2.0f * b0.w);
            Bh[4]  = __float2half2_rn(2.0f * b1.x);
            Bh[5]  = __float2half2_rn(2.0f * b1.y);
            Bh[6]  = __float2half2_rn(2.0f * b1.z);
            Bh[7]  = __float2half2_rn(2.0f * b1.w);
            Bh[8]  = __float2half2_rn(2.0f * b2.x);
            Bh[9]  = __float2half2_rn(2.0f * b2.y);
            Bh[10] = __float2half2_rn(2.0f * b2.z);
            Bh[11] = __float2half2_rn(2.0f * b2.w);
            Bh[12] = __float2half2_rn(2.0f * b3.x);
            Bh[13] = __float2half2_rn(2.0f * b3.y);
            Bh[14] = __float2half2_rn(2.0f * b3.z);
            Bh[15] = __float2half2_rn(2.0f * b3.w);
        }
        const float s = scales[(size_t)row_g * 64 + kt];
        const float step = 2.0f / 15.0f;
        const uint4* qv = (const uint4*)qweight;
        uint4* dst = g_Wp + (size_t)b * 2048 + t * 8;

#pragma unroll
        for (int ch = 0; ch < 8; ch++) {
            __half2 l2[4];
            l2[0] = __float2half2_rn(0.0f);
            l2[1] = l2[0]; l2[2] = l2[0]; l2[3] = l2[0];
#pragma unroll
            for (int r = 0; r < R_LORA; r++) {
                uint4 av = *(const uint4*)&sA2[r][ch * 4];
                l2[0] = __hfma2(Bh[r], *(__half2*)&av.x, l2[0]);
                l2[1] = __hfma2(Bh[r], *(__half2*)&av.y, l2[1]);
                l2[2] = __hfma2(Bh[r], *(__half2*)&av.z, l2[2]);
                l2[3] = __hfma2(Bh[r], *(__half2*)&av.w, l2[3]);
            }
            float2 lf0 = __half22float2(l2[0]);
            float2 lf1 = __half22float2(l2[1]);
            float2 lf2 = __half22float2(l2[2]);
            float2 lf3 = __half22float2(l2[3]);

            uint4 q = qv[(size_t)row_g * 512 + kt * 8 + ch];
            float w[8];
            w[0] = fmaf(fmaf((float)(q.x & 15),        step, -1.0f), s, lf0.x);
            w[1] = fmaf(fmaf((float)((q.x >> 4) & 15), step, -1.0f), s, lf0.y);
            w[2] = fmaf(fmaf((float)(q.y & 15),        step, -1.0f), s, lf1.x);
            w[3] = fmaf(fmaf((float)((q.y >> 4) & 15), step, -1.0f), s, lf1.y);
            w[4] = fmaf(fmaf((float)(q.z & 15),        step, -1.0f), s, lf2.x);
            w[5] = fmaf(fmaf((float)((q.z >> 4) & 15), step, -1.0f), s, lf2.y);
            w[6] = fmaf(fmaf((float)(q.w & 15),        step, -1.0f), s, lf3.x);
            w[7] = fmaf(fmaf((float)((q.w >> 4) & 15), step, -1.0f), s, lf3.y);

            uint4 o;
            o.x = h2_u32(__floats2half2_rn(w[0], w[1]));
            o.y = h2_u32(__floats2half2_rn(w[2], w[3]));
            o.z = h2_u32(__floats2half2_rn(w[4], w[5]));
            o.w = h2_u32(__floats2half2_rn(w[6], w[7]));
            dst[ch ^ (t & 7)] = o;
        }
    } else if (b < 2048) {
        // ---- X tile: 128 rows x 64 cols ----
        const int bb = b - 1024;
        const int mt = bb >> 6;
        const int kt = bb & 63;
        uint4* dst = g_Xp + (size_t)bb * 1024;
#pragma unroll
        for (int i = 0; i < 4; i++) {
            int c   = t + i * 256;
            int row = c >> 3;
            int ch  = c & 7;
            const float* src = x + ((size_t)(mt * 128 + row)) * IN_F + kt * 64 + ch * 8;
            float4 v0 = *(const float4*)(src);
            float4 v1 = *(const float4*)(src + 4);
            uint4 o;
            o.x = h2_u32(__floats2half2_rn(v0.x, v0.y));
            o.y = h2_u32(__floats2half2_rn(v0.z, v0.w));
            o.z = h2_u32(__floats2half2_rn(v1.x, v1.y));
            o.w = h2_u32(__floats2half2_rn(v1.z, v1.w));
            dst[row * 8 + (ch ^ (row & 7))] = o;
        }
    } else {
        // ---- bias broadcast: 8 rows per block ----
        const int bb = b - 2048;                // 0..255
        const int m0 = bb * 8;
        const float4* bsrc = (const float4*)bias + t * 4;   // cols t*16..+15
        float4 b0 = bsrc[0], b1 = bsrc[1], b2 = bsrc[2], b3 = bsrc[3];
#pragma unroll
        for (int r = 0; r < 8; r++) {
            float4* dst = (float4*)(out + (size_t)(m0 + r) * OUT_F) + t * 4;
            dst[0] = b0; dst[1] = b1; dst[2] = b2; dst[3] = b3;
        }
    }
}

// ---------------------------------------------------------------------------
// GEMM body (shared by full and quarter kernels).
// CTA tile 128x256, BK=64, 4-stage cp.async, 16 warps (2M x 8N).
// ---------------------------------------------------------------------------
template <bool ATOMIC>
__device__ __forceinline__ void gemm_tile(uint4* smem,
                                          const float* __restrict__ bias,
                                          float* __restrict__ out,
                                          int mt, int nt, int it0, int niter)
{
    const uint32_t sbase = smem_u32(smem);
    const int t    = threadIdx.x;
    const int lane = t & 31;
    const int wid  = t >> 5;
    const int g4   = lane >> 2;
    const int l4   = lane & 3;
    const int wm   = wid & 1;
    const int wn   = wid >> 1;

    const int ar = lane & 7;
    const int ag = lane >> 3;
    const int rg = ag & 1;
    const int cg = ag >> 1;
    const uint32_t arow_off = (uint32_t)(wm * 64 + rg * 8 + ar) * 128u;
    const uint32_t brow_off = (uint32_t)(wn * 32 + rg * 8 + ar) * 128u;
    uint32_t sw[4];
#pragma unroll
    for (int ks = 0; ks < 4; ks++)
        sw[ks] = (uint32_t)(((ks * 2 + cg) ^ ar) * 16);

    const uint4* srcA0 = g_Xp + (size_t)mt * 64 * 1024 + (size_t)it0 * 1024;
    const uint4* srcB0 = g_Wp + (size_t)nt * 64 * 2048 + (size_t)it0 * 2048;

    float acc[4][4][4];
#pragma unroll
    for (int mf = 0; mf < 4; mf++)
#pragma unroll
        for (int nf = 0; nf < 4; nf++)
#pragma unroll
            for (int j = 0; j < 4; j++) acc[mf][nf][j] = 0.0f;

    auto load_stage = [&](int it, int s) {
        uint32_t d = sbase + (uint32_t)(s * STAGE_CHUNKS * 16);
        const uint4* sa = srcA0 + (size_t)it * 1024;
        const uint4* sb = srcB0 + (size_t)it * 2048;
#pragma unroll
        for (int i = 0; i < 2; i++)
            cp_async16(d + (t + i * NTHREADS) * 16, sa + t + i * NTHREADS);
        d += 1024 * 16;
#pragma unroll
        for (int i = 0; i < 4; i++)
            cp_async16(d + (t + i * NTHREADS) * 16, sb + t + i * NTHREADS);
        asm volatile("cp.async.commit_group;" ::: "memory");
    };

    load_stage(0, 0);
    load_stage(1, 1);
    load_stage(2, 2);

#pragma unroll 1
    for (int it = 0; it < niter; ++it) {
        if (it < niter - 2)
            asm volatile("cp.async.wait_group 2;" ::: "memory");
        else if (it == niter - 2)
            asm volatile("cp.async.wait_group 1;" ::: "memory");
        else
            asm volatile("cp.async.wait_group 0;" ::: "memory");
        __syncthreads();

        if (it + 3 < niter) load_stage(it + 3, (it + 3) % STAGES);

        const uint32_t aS = sbase + (uint32_t)((it % STAGES) * STAGE_CHUNKS * 16);
        const uint32_t bS = aS + 1024 * 16;

#pragma unroll
        for (int ks = 0; ks < 4; ks++) {
            uint32_t a[4][4], b[2][4];
#pragma unroll
            for (int mf = 0; mf < 4; mf++)
                ldmx4(a[mf], aS + arow_off + mf * 2048 + sw[ks]);
#pragma unroll
            for (int p = 0; p < 2; p++)
                ldmx4(b[p], bS + brow_off + p * 2048 + sw[ks]);

#pragma unroll
            for (int mf = 0; mf < 4; mf++)
#pragma unroll
                for (int p = 0; p < 2; p++) {
                    mma_f16(acc[mf][2 * p],     a[mf], b[p][0], b[p][2]);
                    mma_f16(acc[mf][2 * p + 1], a[mf], b[p][1], b[p][3]);
                }
        }
    }

    const int m0 = mt * 128 + wm * 64;
    const int n0 = nt * 256 + wn * 32;

    if (!ATOMIC) {
        float2 bb[4];
#pragma unroll
        for (int nf = 0; nf < 4; nf++)
            bb[nf] = *(const float2*)(bias + n0 + nf * 8 + l4 * 2);
#pragma unroll
        for (int mf = 0; mf < 4; mf++) {
            const int m = m0 + mf * 16 + g4;
            float* r0 = out + (size_t)m * OUT_F;
            float* r1 = out + (size_t)(m + 8) * OUT_F;
#pragma unroll
            for (int nf = 0; nf < 4; nf++) {
                const int n = n0 + nf * 8 + l4 * 2;
                float2 v0, v1;
                v0.x = acc[mf][nf][0] + bb[nf].x;
                v0.y = acc[mf][nf][1] + bb[nf].y;
                v1.x = acc[mf][nf][2] + bb[nf].x;
                v1.y = acc[mf][nf][3] + bb[nf].y;
                *(float2*)(r0 + n) = v0;
                *(float2*)(r1 + n) = v1;
            }
        }
    } else {
#pragma unroll
        for (int mf = 0; mf < 4; mf++) {
            const int m = m0 + mf * 16 + g4;
            float* r0 = out + (size_t)m * OUT_F;
            float* r1 = out + (size_t)(m + 8) * OUT_F;
#pragma unroll
            for (int nf = 0; nf < 4; nf++) {
                const int n = n0 + nf * 8 + l4 * 2;
                atomicAdd(r0 + n,     acc[mf][nf][0]);
                atomicAdd(r0 + n + 1, acc[mf][nf][1]);
                atomicAdd(r1 + n,     acc[mf][nf][2]);
                atomicAdd(r1 + n + 1, acc[mf][nf][3]);
            }
        }
    }
}

// Full tiles 0..147 (one exact wave): direct store with bias.
__global__ __launch_bounds__(NTHREADS, 1)
void gemm_full_kernel(const float* __restrict__ bias, float* __restrict__ out)
{
    extern __shared__ uint4 smem[];
    const int tile = blockIdx.x;           // 0..147
    gemm_tile<false>(smem, bias, out, tile & 15, tile >> 4, 0, 64);
}

// Quarter tiles of output tiles 148..255: K split into 4, atomicAdd.
__global__ __launch_bounds__(NTHREADS, 1)
void gemm_quarter_kernel(float* __restrict__ out)
{
    extern __shared__ uint4 smem[];
    const int q    = blockIdx.x;            // 0..431
    const int tile = 148 + (q >> 2);        // 148..255
    const int ks   = q & 3;
    gemm_tile<true>(smem, nullptr, out, tile & 15, tile >> 4, ks * 16, 16);
}

// ---------------------------------------------------------------------------
// Launch: x, qweight, scales, bias, lora_A, lora_B
// ---------------------------------------------------------------------------
extern "C" void kernel_launch(void* const* d_in, const int* in_sizes, int n_in,
                              void* d_out, int out_size)
{
    const float* x      = (const float*)d_in[0];
    const int*   qw     = (const int*)  d_in[1];
    const float* scales = (const float*)d_in[2];
    const float* bias   = (const float*)d_in[3];
    const float* lora_A = (const float*)d_in[4];
    const float* lora_B = (const float*)d_in[5];
    float*       out    = (float*)d_out;
    (void)in_sizes; (void)n_in; (void)out_size;

    cudaFuncSetAttribute(gemm_full_kernel,
                         cudaFuncAttributeMaxDynamicSharedMemorySize, SMEM_BYTES);
    cudaFuncSetAttribute(gemm_quarter_kernel,
                         cudaFuncAttributeMaxDynamicSharedMemorySize, SMEM_BYTES);

    prep_kernel<<<2304, 256>>>(x, qw, scales, lora_A, lora_B, bias, out);
    gemm_full_kernel<<<148, NTHREADS, SMEM_BYTES>>>(bias, out);
    gemm_quarter_kernel<<<432, NTHREADS, SMEM_BYTES>>>(out);
}

// round 14
// speedup vs baseline: 1.0677x; 1.0572x over previous
#include <cuda_runtime.h>
#include <cuda_fp16.h>
#include <cstdint>

// ---------------------------------------------------------------------------
// BaseLoftqLinear:
//   W' = dequant4(q, s) + 2.0 * (B @ A);   out = x @ W'^T + bias
// fp16 mma.sync.m16n8k16 (fp32 accum), pre-packed/pre-swizzled operands.
// Wave-tail fix: one GEMM launch, blocks 0..147 = full tiles (exact wave 1,
// direct store), blocks 148..579 = K-quarter tiles of output tiles 148..255
// (atomicAdd onto bias-pre-initialized region; init covers ONLY those tiles).
// ---------------------------------------------------------------------------

#define OUT_F 4096
#define IN_F  4096
#define M_TOK 2048
#define R_LORA 16

// packed 16B-chunk layouts (chunk stored at ch ^ (row&7)):
//   X: [mt(16)][kt(64)][row(128)][chunk(8)]
//   W: [nt(16)][kt(64)][row(256)][chunk(8)]
__device__ uint4 g_Xp[(size_t)M_TOK * IN_F / 8];   // 16 MB
__device__ uint4 g_Wp[(size_t)OUT_F * IN_F / 8];   // 32 MB

#define NTHREADS 512
#define STAGES 4
#define STAGE_CHUNKS 3072                           // A 1024 + B 2048 (16B each)
#define SMEM_BYTES (STAGES * STAGE_CHUNKS * 16)     // 196608

__device__ __forceinline__ uint32_t smem_u32(const void* p) {
    uint32_t a;
    asm("{ .reg .u64 t; cvta.to.shared.u64 t, %1; cvt.u32.u64 %0, t; }"
        : "=r"(a) : "l"(p));
    return a;
}

__device__ __forceinline__ uint32_t h2_u32(__half2 h) {
    union { __half2 h; uint32_t u; } cvt;
    cvt.h = h;
    return cvt.u;
}

__device__ __forceinline__ void cp_async16(uint32_t dst, const void* src) {
    asm volatile("cp.async.cg.shared.global [%0], [%1], 16;"
                 :: "r"(dst), "l"(src) : "memory");
}

__device__ __forceinline__ void ldmx4(uint32_t* r, uint32_t addr) {
    asm volatile("ldmatrix.sync.aligned.m8n8.x4.shared.b16 {%0,%1,%2,%3}, [%4];"
                 : "=r"(r[0]), "=r"(r[1]), "=r"(r[2]), "=r"(r[3]) : "r"(addr));
}

__device__ __forceinline__ void mma_f16(float* d, const uint32_t* a,
                                        uint32_t b0, uint32_t b1) {
    asm volatile(
        "mma.sync.aligned.m16n8k16.row.col.f32.f16.f16.f32 "
        "{%0,%1,%2,%3}, {%4,%5,%6,%7}, {%8,%9}, {%0,%1,%2,%3};"
        : "+f"(d[0]), "+f"(d[1]), "+f"(d[2]), "+f"(d[3])
        : "r"(a[0]), "r"(a[1]), "r"(a[2]), "r"(a[3]), "r"(b0), "r"(b1));
}

// ---------------------------------------------------------------------------
// Prep kernel: blocks 0..1023 = W tiles, 1024..2047 = X tiles,
//              2048..2155 = bias init for output tiles 148..255 only.
// ---------------------------------------------------------------------------
__global__ __launch_bounds__(256)
void prep_kernel(const float* __restrict__ x,
                 const int* __restrict__ qweight,
                 const float* __restrict__ scales,
                 const float* __restrict__ lora_A,   // [R, IN_F]
                 const float* __restrict__ lora_B,   // [OUT_F, R]
                 const float* __restrict__ bias,
                 float* __restrict__ out)
{
    const int t = threadIdx.x;
    const int b = blockIdx.x;

    if (b < 1024) {
        // ---- W tile: nt = b>>6, kt = b&63; 256 rows x 64 cols ----
        __shared__ __half2 sA2[R_LORA][32];
        const int nt = b >> 6;
        const int kt = b & 63;

        {
            int r  = t >> 4;
            int c4 = t & 15;
            float4 a = *(const float4*)(lora_A + (size_t)r * IN_F + kt * 64 + c4 * 4);
            sA2[r][c4 * 2]     = __floats2half2_rn(a.x, a.y);
            sA2[r][c4 * 2 + 1] = __floats2half2_rn(a.z, a.w);
        }
        __syncthreads();

        const int row_g = nt * 256 + t;
        __half2 Bh[R_LORA];
        {
            float4 b0 = *(const float4*)(lora_B + (size_t)row_g * R_LORA + 0);
            float4 b1 = *(const float4*)(lora_B + (size_t)row_g * R_LORA + 4);
            float4 b2 = *(const float4*)(lora_B + (size_t)row_g * R_LORA + 8);
            float4 b3 = *(const float4*)(lora_B + (size_t)row_g * R_LORA + 12);
            Bh[0]  = __float2half2_rn(2.0f * b0.x);
            Bh[1]  = __float2half2_rn(2.0f * b0.y);
            Bh[2]  = __float2half2_rn(2.0f * b0.z);
            Bh[3]  = __float2half2_rn(2.0f * b0.w);
            Bh[4]  = __float2half2_rn(2.0f * b1.x);
            Bh[5]  = __float2half2_rn(2.0f * b1.y);
            Bh[6]  = __float2half2_rn(2.0f * b1.z);
            Bh[7]  = __float2half2_rn(2.0f * b1.w);
            Bh[8]  = __float2half2_rn(2.0f * b2.x);
            Bh[9]  = __float2half2_rn(2.0f * b2.y);
            Bh[10] = __float2half2_rn(2.0f * b2.z);
            Bh[11] = __float2half2_rn(2.0f * b2.w);
            Bh[12] = __float2half2_rn(2.0f * b3.x);
            Bh[13] = __float2half2_rn(2.0f * b3.y);
            Bh[14] = __float2half2_rn(2.0f * b3.z);
            Bh[15] = __float2half2_rn(2.0f * b3.w);
        }
        const float s = scales[(size_t)row_g * 64 + kt];
        const float step = 2.0f / 15.0f;
        const uint4* qv = (const uint4*)qweight;
        uint4* dst = g_Wp + (size_t)b * 2048 + t * 8;

#pragma unroll
        for (int ch = 0; ch < 8; ch++) {
            __half2 l2[4];
            l2[0] = __float2half2_rn(0.0f);
            l2[1] = l2[0]; l2[2] = l2[0]; l2[3] = l2[0];
#pragma unroll
            for (int r = 0; r < R_LORA; r++) {
                uint4 av = *(const uint4*)&sA2[r][ch * 4];
                l2[0] = __hfma2(Bh[r], *(__half2*)&av.x, l2[0]);
                l2[1] = __hfma2(Bh[r], *(__half2*)&av.y, l2[1]);
                l2[2] = __hfma2(Bh[r], *(__half2*)&av.z, l2[2]);
                l2[3] = __hfma2(Bh[r], *(__half2*)&av.w, l2[3]);
            }
            float2 lf0 = __half22float2(l2[0]);
            float2 lf1 = __half22float2(l2[1]);
            float2 lf2 = __half22float2(l2[2]);
            float2 lf3 = __half22float2(l2[3]);

            uint4 q = qv[(size_t)row_g * 512 + kt * 8 + ch];
            float w[8];
            w[0] = fmaf(fmaf((float)(q.x & 15),        step, -1.0f), s, lf0.x);
            w[1] = fmaf(fmaf((float)((q.x >> 4) & 15), step, -1.0f), s, lf0.y);
            w[2] = fmaf(fmaf((float)(q.y & 15),        step, -1.0f), s, lf1.x);
            w[3] = fmaf(fmaf((float)((q.y >> 4) & 15), step, -1.0f), s, lf1.y);
            w[4] = fmaf(fmaf((float)(q.z & 15),        step, -1.0f), s, lf2.x);
            w[5] = fmaf(fmaf((float)((q.z >> 4) & 15), step, -1.0f), s, lf2.y);
            w[6] = fmaf(fmaf((float)(q.w & 15),        step, -1.0f), s, lf3.x);
            w[7] = fmaf(fmaf((float)((q.w >> 4) & 15), step, -1.0f), s, lf3.y);

            uint4 o;
            o.x = h2_u32(__floats2half2_rn(w[0], w[1]));
            o.y = h2_u32(__floats2half2_rn(w[2], w[3]));
            o.z = h2_u32(__floats2half2_rn(w[4], w[5]));
            o.w = h2_u32(__floats2half2_rn(w[6], w[7]));
            dst[ch ^ (t & 7)] = o;
        }
    } else if (b < 2048) {
        // ---- X tile: 128 rows x 64 cols ----
        const int bb = b - 1024;
        const int mt = bb >> 6;
        const int kt = bb & 63;
        uint4* dst = g_Xp + (size_t)bb * 1024;
#pragma unroll
        for (int i = 0; i < 4; i++) {
            int c   = t + i * 256;
            int row = c >> 3;
            int ch  = c & 7;
            const float* src = x + ((size_t)(mt * 128 + row)) * IN_F + kt * 64 + ch * 8;
            float4 v0 = *(const float4*)(src);
            float4 v1 = *(const float4*)(src + 4);
            uint4 o;
            o.x = h2_u32(__floats2half2_rn(v0.x, v0.y));
            o.y = h2_u32(__floats2half2_rn(v0.z, v0.w));
            o.z = h2_u32(__floats2half2_rn(v1.x, v1.y));
            o.w = h2_u32(__floats2half2_rn(v1.z, v1.w));
            dst[row * 8 + (ch ^ (row & 7))] = o;
        }
    } else {
        // ---- bias init for output tile 148 + (b - 2048) ----
        const int tile = 148 + (b - 2048);      // 148..255
        const int mt = tile & 15;
        const int nt = tile >> 4;
        const int m0 = mt * 128;
        const int n0 = nt * 256;
        const int c4 = t & 63;                  // f4-col within 256-col tile
        const int rg = t >> 6;                  // row-group 0..3 (32 rows each)
        float4 bv = ((const float4*)(bias + n0))[c4];
        float4* base = (float4*)(out + (size_t)(m0 + rg * 32) * OUT_F + n0) + c4;
#pragma unroll
        for (int r = 0; r < 32; r++)
            base[(size_t)r * (OUT_F / 4)] = bv;
    }
}

// ---------------------------------------------------------------------------
// GEMM tile body. CTA tile 128x256, BK=64, 4-stage cp.async, 16 warps (2Mx8N).
// ---------------------------------------------------------------------------
template <bool ATOMIC>
__device__ __forceinline__ void gemm_tile(uint4* smem,
                                          const float* __restrict__ bias,
                                          float* __restrict__ out,
                                          int mt, int nt, int it0, int niter)
{
    const uint32_t sbase = smem_u32(smem);
    const int t    = threadIdx.x;
    const int lane = t & 31;
    const int wid  = t >> 5;
    const int g4   = lane >> 2;
    const int l4   = lane & 3;
    const int wm   = wid & 1;
    const int wn   = wid >> 1;

    const int ar = lane & 7;
    const int ag = lane >> 3;
    const int rg = ag & 1;
    const int cg = ag >> 1;
    const uint32_t arow_off = (uint32_t)(wm * 64 + rg * 8 + ar) * 128u;
    const uint32_t brow_off = (uint32_t)(wn * 32 + rg * 8 + ar) * 128u;
    uint32_t sw[4];
#pragma unroll
    for (int ks = 0; ks < 4; ks++)
        sw[ks] = (uint32_t)(((ks * 2 + cg) ^ ar) * 16);

    const uint4* srcA0 = g_Xp + (size_t)mt * 64 * 1024 + (size_t)it0 * 1024;
    const uint4* srcB0 = g_Wp + (size_t)nt * 64 * 2048 + (size_t)it0 * 2048;

    float acc[4][4][4];
#pragma unroll
    for (int mf = 0; mf < 4; mf++)
#pragma unroll
        for (int nf = 0; nf < 4; nf++)
#pragma unroll
            for (int j = 0; j < 4; j++) acc[mf][nf][j] = 0.0f;

    auto load_stage = [&](int it, int s) {
        uint32_t d = sbase + (uint32_t)(s * STAGE_CHUNKS * 16);
        const uint4* sa = srcA0 + (size_t)it * 1024;
        const uint4* sb = srcB0 + (size_t)it * 2048;
#pragma unroll
        for (int i = 0; i < 2; i++)
            cp_async16(d + (t + i * NTHREADS) * 16, sa + t + i * NTHREADS);
        d += 1024 * 16;
#pragma unroll
        for (int i = 0; i < 4; i++)
            cp_async16(d + (t + i * NTHREADS) * 16, sb + t + i * NTHREADS);
        asm volatile("cp.async.commit_group;" ::: "memory");
    };

    load_stage(0, 0);
    load_stage(1, 1);
    load_stage(2, 2);

#pragma unroll 1
    for (int it = 0; it < niter; ++it) {
        if (it < niter - 2)
            asm volatile("cp.async.wait_group 2;" ::: "memory");
        else if (it == niter - 2)
            asm volatile("cp.async.wait_group 1;" ::: "memory");
        else
            asm volatile("cp.async.wait_group 0;" ::: "memory");
        __syncthreads();

        if (it + 3 < niter) load_stage(it + 3, (it + 3) % STAGES);

        const uint32_t aS = sbase + (uint32_t)((it % STAGES) * STAGE_CHUNKS * 16);
        const uint32_t bS = aS + 1024 * 16;

#pragma unroll
        for (int ks = 0; ks < 4; ks++) {
            uint32_t a[4][4], b[2][4];
#pragma unroll
            for (int mf = 0; mf < 4; mf++)
                ldmx4(a[mf], aS + arow_off + mf * 2048 + sw[ks]);
#pragma unroll
            for (int p = 0; p < 2; p++)
                ldmx4(b[p], bS + brow_off + p * 2048 + sw[ks]);

#pragma unroll
            for (int mf = 0; mf < 4; mf++)
#pragma unroll
                for (int p = 0; p < 2; p++) {
                    mma_f16(acc[mf][2 * p],     a[mf], b[p][0], b[p][2]);
                    mma_f16(acc[mf][2 * p + 1], a[mf], b[p][1], b[p][3]);
                }
        }
    }

    const int m0 = mt * 128 + wm * 64;
    const int n0 = nt * 256 + wn * 32;

    if (!ATOMIC) {
        float2 bb[4];
#pragma unroll
        for (int nf = 0; nf < 4; nf++)
            bb[nf] = *(const float2*)(bias + n0 + nf * 8 + l4 * 2);
#pragma unroll
        for (int mf = 0; mf < 4; mf++) {
            const int m = m0 + mf * 16 + g4;
            float* r0 = out + (size_t)m * OUT_F;
            float* r1 = out + (size_t)(m + 8) * OUT_F;
#pragma unroll
            for (int nf = 0; nf < 4; nf++) {
                const int n = n0 + nf * 8 + l4 * 2;
                float2 v0, v1;
                v0.x = acc[mf][nf][0] + bb[nf].x;
                v0.y = acc[mf][nf][1] + bb[nf].y;
                v1.x = acc[mf][nf][2] + bb[nf].x;
                v1.y = acc[mf][nf][3] + bb[nf].y;
                *(float2*)(r0 + n) = v0;
                *(float2*)(r1 + n) = v1;
            }
        }
    } else {
#pragma unroll
        for (int mf = 0; mf < 4; mf++) {
            const int m = m0 + mf * 16 + g4;
            float* r0 = out + (size_t)m * OUT_F;
            float* r1 = out + (size_t)(m + 8) * OUT_F;
#pragma unroll
            for (int nf = 0; nf < 4; nf++) {
                const int n = n0 + nf * 8 + l4 * 2;
                atomicAdd(r0 + n,     acc[mf][nf][0]);
                atomicAdd(r0 + n + 1, acc[mf][nf][1]);
                atomicAdd(r1 + n,     acc[mf][nf][2]);
                atomicAdd(r1 + n + 1, acc[mf][nf][3]);
            }
        }
    }
}

// Single GEMM launch: blocks 0..147 full tiles (wave 1), 148..579 quarters.
__global__ __launch_bounds__(NTHREADS, 1)
void gemm_kernel(const float* __restrict__ bias, float* __restrict__ out)
{
    extern __shared__ uint4 smem[];
    const int c = blockIdx.x;
    if (c < 148) {
        gemm_tile<false>(smem, bias, out, c & 15, c >> 4, 0, 64);
    } else {
        const int q    = c - 148;               // 0..431
        const int tile = 148 + (q >> 2);        // 148..255
        const int ks   = q & 3;
        gemm_tile<true>(smem, nullptr, out, tile & 15, tile >> 4, ks * 16, 16);
    }
}

// ---------------------------------------------------------------------------
// Launch: x, qweight, scales, bias, lora_A, lora_B
// ---------------------------------------------------------------------------
extern "C" void kernel_launch(void* const* d_in, const int* in_sizes, int n_in,
                              void* d_out, int out_size)
{
    const float* x      = (const float*)d_in[0];
    const int*   qw     = (const int*)  d_in[1];
    const float* scales = (const float*)d_in[2];
    const float* bias   = (const float*)d_in[3];
    const float* lora_A = (const float*)d_in[4];
    const float* lora_B = (const float*)d_in[5];
    float*       out    = (float*)d_out;
    (void)in_sizes; (void)n_in; (void)out_size;

    cudaFuncSetAttribute(gemm_kernel,
                         cudaFuncAttributeMaxDynamicSharedMemorySize, SMEM_BYTES);

    prep_kernel<<<2156, 256>>>(x, qw, scales, lora_A, lora_B, bias, out);
    gemm_kernel<<<580, NTHREADS, SMEM_BYTES>>>(bias, out);
}

// round 15
// speedup vs baseline: 1.0889x; 1.0199x over previous
#include <cuda_runtime.h>
#include <cuda_fp16.h>
#include <cstdint>

// ---------------------------------------------------------------------------
// BaseLoftqLinear:
//   W' = dequant4(q, s) + 2.0 * (B @ A);   out = x @ W'^T + bias
// fp16 mma.sync.m16n8k16 (fp32 accum), pre-packed/pre-swizzled operands.
// GEMM: one launch, blocks 0..147 = full tiles (exact wave 1, direct store),
// blocks 148..579 = K-quarter tiles of output tiles 148..255 (atomicAdd onto
// bias-pre-initialized region).
// Prep: 512-thread blocks, bias-init first, W/X work interleaved so each
// resident wave mixes compute-bound and memory-bound blocks.
// ---------------------------------------------------------------------------

#define OUT_F 4096
#define IN_F  4096
#define M_TOK 2048
#define R_LORA 16

// packed 16B-chunk layouts (chunk stored at ch ^ (row&7)):
//   X: [mt(16)][kt(64)][row(128)][chunk(8)]
//   W: [nt(16)][kt(64)][row(256)][chunk(8)]
__device__ uint4 g_Xp[(size_t)M_TOK * IN_F / 8];   // 16 MB
__device__ uint4 g_Wp[(size_t)OUT_F * IN_F / 8];   // 32 MB

#define NTHREADS 512
#define STAGES 4
#define STAGE_CHUNKS 3072                           // A 1024 + B 2048 (16B each)
#define SMEM_BYTES (STAGES * STAGE_CHUNKS * 16)     // 196608

__device__ __forceinline__ uint32_t smem_u32(const void* p) {
    uint32_t a;
    asm("{ .reg .u64 t; cvta.to.shared.u64 t, %1; cvt.u32.u64 %0, t; }"
        : "=r"(a) : "l"(p));
    return a;
}

__device__ __forceinline__ uint32_t h2_u32(__half2 h) {
    union { __half2 h; uint32_t u; } cvt;
    cvt.h = h;
    return cvt.u;
}

__device__ __forceinline__ void cp_async16(uint32_t dst, const void* src) {
    asm volatile("cp.async.cg.shared.global [%0], [%1], 16;"
                 :: "r"(dst), "l"(src) : "memory");
}

__device__ __forceinline__ void ldmx4(uint32_t* r, uint32_t addr) {
    asm volatile("ldmatrix.sync.aligned.m8n8.x4.shared.b16 {%0,%1,%2,%3}, [%4];"
                 : "=r"(r[0]), "=r"(r[1]), "=r"(r[2]), "=r"(r[3]) : "r"(addr));
}

__device__ __forceinline__ void mma_f16(float* d, const uint32_t* a,
                                        uint32_t b0, uint32_t b1) {
    asm volatile(
        "mma.sync.aligned.m16n8k16.row.col.f32.f16.f16.f32 "
        "{%0,%1,%2,%3}, {%4,%5,%6,%7}, {%8,%9}, {%0,%1,%2,%3};"
        : "+f"(d[0]), "+f"(d[1]), "+f"(d[2]), "+f"(d[3])
        : "r"(a[0]), "r"(a[1]), "r"(a[2]), "r"(a[3]), "r"(b0), "r"(b1));
}

// ---------------------------------------------------------------------------
// Prep kernel (512 threads/block):
//   blocks 0..107            : bias init for output tiles 148..255
//   blocks 108..2155, even   : W tile (ib>>1)
//   blocks 108..2155, odd    : X tile (ib>>1)
// ---------------------------------------------------------------------------
__global__ __launch_bounds__(512)
void prep_kernel(const float* __restrict__ x,
                 const int* __restrict__ qweight,
                 const float* __restrict__ scales,
                 const float* __restrict__ lora_A,   // [R, IN_F]
                 const float* __restrict__ lora_B,   // [OUT_F, R]
                 const float* __restrict__ bias,
                 float* __restrict__ out)
{
    const int t = threadIdx.x;
    const int b = blockIdx.x;

    if (b < 108) {
        // ---- bias init for output tile 148 + b ----
        const int tile = 148 + b;               // 148..255
        const int mt = tile & 15;
        const int nt = tile >> 4;
        const int m0 = mt * 128;
        const int n0 = nt * 256;
        const int c4 = t & 63;                  // f4-col within 256-col tile
        const int rg = t >> 6;                  // row-group 0..7 (16 rows each)
        float4 bv = ((const float4*)(bias + n0))[c4];
        float4* base = (float4*)(out + (size_t)(m0 + rg * 16) * OUT_F + n0) + c4;
#pragma unroll
        for (int r = 0; r < 16; r++)
            base[(size_t)r * (OUT_F / 4)] = bv;
        return;
    }

    const int ib   = b - 108;                   // 0..2047
    const int item = ib >> 1;                   // 0..1023

    if ((ib & 1) == 0) {
        // ---- W tile: nt = item>>6, kt = item&63; 256 rows x 64 cols ----
        __shared__ __half2 sA2[R_LORA][32];     // A slice as half2 (2 KB)
        const int nt = item >> 6;
        const int kt = item & 63;

        if (t < 256) {
            int r  = t >> 4;
            int c4 = t & 15;
            float4 a = *(const float4*)(lora_A + (size_t)r * IN_F + kt * 64 + c4 * 4);
            sA2[r][c4 * 2]     = __floats2half2_rn(a.x, a.y);
            sA2[r][c4 * 2 + 1] = __floats2half2_rn(a.z, a.w);
        }
        __syncthreads();

        const int row   = t >> 1;               // 0..255
        const int hlf   = t & 1;                 // chunks [hlf*4, hlf*4+4)
        const int row_g = nt * 256 + row;

        __half2 Bh[R_LORA];
        {
            float4 b0 = *(const float4*)(lora_B + (size_t)row_g * R_LORA + 0);
            float4 b1 = *(const float4*)(lora_B + (size_t)row_g * R_LORA + 4);
            float4 b2 = *(const float4*)(lora_B + (size_t)row_g * R_LORA + 8);
            float4 b3 = *(const float4*)(lora_B + (size_t)row_g * R_LORA + 12);
            Bh[0]  = __float2half2_rn(2.0f * b0.x);
            Bh[1]  = __float2half2_rn(2.0f * b0.y);
            Bh[2]  = __float2half2_rn(2.0f * b0.z);
            Bh[3]  = __float2half2_rn(2.0f * b0.w);
            Bh[4]  = __float2half2_rn(2.0f * b1.x);
            Bh[5]  = __float2half2_rn(2.0f * b1.y);
            Bh[6]  = __float2half2_rn(2.0f * b1.z);
            Bh[7]  = __float2half2_rn(2.0f * b1.w);
            Bh[8]  = __float2half2_rn(2.0f * b2.x);
            Bh[9]  = __float2half2_rn(2.0f * b2.y);
            Bh[10] = __float2half2_rn(2.0f * b2.z);
            Bh[11] = __float2half2_rn(2.0f * b2.w);
            Bh[12] = __float2half2_rn(2.0f * b3.x);
            Bh[13] = __float2half2_rn(2.0f * b3.y);
            Bh[14] = __float2half2_rn(2.0f * b3.z);
            Bh[15] = __float2half2_rn(2.0f * b3.w);
        }
        const float s = scales[(size_t)row_g * 64 + kt];
        const float step = 2.0f / 15.0f;
        const uint4* qv = (const uint4*)qweight;
        uint4* dst = g_Wp + (size_t)item * 2048 + row * 8;

#pragma unroll
        for (int j = 0; j < 4; j++) {
            const int ch = hlf * 4 + j;
            __half2 l2[4];
            l2[0] = __float2half2_rn(0.0f);
            l2[1] = l2[0]; l2[2] = l2[0]; l2[3] = l2[0];
#pragma unroll
            for (int r = 0; r < R_LORA; r++) {
                uint4 av = *(const uint4*)&sA2[r][ch * 4];
                l2[0] = __hfma2(Bh[r], *(__half2*)&av.x, l2[0]);
                l2[1] = __hfma2(Bh[r], *(__half2*)&av.y, l2[1]);
                l2[2] = __hfma2(Bh[r], *(__half2*)&av.z, l2[2]);
                l2[3] = __hfma2(Bh[r], *(__half2*)&av.w, l2[3]);
            }
            float2 lf0 = __half22float2(l2[0]);
            float2 lf1 = __half22float2(l2[1]);
            float2 lf2 = __half22float2(l2[2]);
            float2 lf3 = __half22float2(l2[3]);

            uint4 q = qv[(size_t)row_g * 512 + kt * 8 + ch];
            float w[8];
            w[0] = fmaf(fmaf((float)(q.x & 15),        step, -1.0f), s, lf0.x);
            w[1] = fmaf(fmaf((float)((q.x >> 4) & 15), step, -1.0f), s, lf0.y);
            w[2] = fmaf(fmaf((float)(q.y & 15),        step, -1.0f), s, lf1.x);
            w[3] = fmaf(fmaf((float)((q.y >> 4) & 15), step, -1.0f), s, lf1.y);
            w[4] = fmaf(fmaf((float)(q.z & 15),        step, -1.0f), s, lf2.x);
            w[5] = fmaf(fmaf((float)((q.z >> 4) & 15), step, -1.0f), s, lf2.y);
            w[6] = fmaf(fmaf((float)(q.w & 15),        step, -1.0f), s, lf3.x);
            w[7] = fmaf(fmaf((float)((q.w >> 4) & 15), step, -1.0f), s, lf3.y);

            uint4 o;
            o.x = h2_u32(__floats2half2_rn(w[0], w[1]));
            o.y = h2_u32(__floats2half2_rn(w[2], w[3]));
            o.z = h2_u32(__floats2half2_rn(w[4], w[5]));
            o.w = h2_u32(__floats2half2_rn(w[6], w[7]));
            dst[ch ^ (row & 7)] = o;
        }
    } else {
        // ---- X tile: 128 rows x 64 cols ----
        const int mt = item >> 6;
        const int kt = item & 63;
        uint4* dst = g_Xp + (size_t)item * 1024;
#pragma unroll
        for (int i = 0; i < 2; i++) {
            int c   = t + i * 512;              // chunk id 0..1023
            int row = c >> 3;
            int ch  = c & 7;
            const float* src = x + ((size_t)(mt * 128 + row)) * IN_F + kt * 64 + ch * 8;
            float4 v0 = *(const float4*)(src);
            float4 v1 = *(const float4*)(src + 4);
            uint4 o;
            o.x = h2_u32(__floats2half2_rn(v0.x, v0.y));
            o.y = h2_u32(__floats2half2_rn(v0.z, v0.w));
            o.z = h2_u32(__floats2half2_rn(v1.x, v1.y));
            o.w = h2_u32(__floats2half2_rn(v1.z, v1.w));
            dst[row * 8 + (ch ^ (row & 7))] = o;
        }
    }
}

// ---------------------------------------------------------------------------
// GEMM tile body. CTA tile 128x256, BK=64, 4-stage cp.async, 16 warps (2Mx8N).
// ---------------------------------------------------------------------------
template <bool ATOMIC>
__device__ __forceinline__ void gemm_tile(uint4* smem,
                                          const float* __restrict__ bias,
                                          float* __restrict__ out,
                                          int mt, int nt, int it0, int niter)
{
    const uint32_t sbase = smem_u32(smem);
    const int t    = threadIdx.x;
    const int lane = t & 31;
    const int wid  = t >> 5;
    const int g4   = lane >> 2;
    const int l4   = lane & 3;
    const int wm   = wid & 1;
    const int wn   = wid >> 1;

    const int ar = lane & 7;
    const int ag = lane >> 3;
    const int rg = ag & 1;
    const int cg = ag >> 1;
    const uint32_t arow_off = (uint32_t)(wm * 64 + rg * 8 + ar) * 128u;
    const uint32_t brow_off = (uint32_t)(wn * 32 + rg * 8 + ar) * 128u;
    uint32_t sw[4];
#pragma unroll
    for (int ks = 0; ks < 4; ks++)
        sw[ks] = (uint32_t)(((ks * 2 + cg) ^ ar) * 16);

    const uint4* srcA0 = g_Xp + (size_t)mt * 64 * 1024 + (size_t)it0 * 1024;
    const uint4* srcB0 = g_Wp + (size_t)nt * 64 * 2048 + (size_t)it0 * 2048;

    float acc[4][4][4];
#pragma unroll
    for (int mf = 0; mf < 4; mf++)
#pragma unroll
        for (int nf = 0; nf < 4; nf++)
#pragma unroll
            for (int j = 0; j < 4; j++) acc[mf][nf][j] = 0.0f;

    auto load_stage = [&](int it, int s) {
        uint32_t d = sbase + (uint32_t)(s * STAGE_CHUNKS * 16);
        const uint4* sa = srcA0 + (size_t)it * 1024;
        const uint4* sb = srcB0 + (size_t)it * 2048;
#pragma unroll
        for (int i = 0; i < 2; i++)
            cp_async16(d + (t + i * NTHREADS) * 16, sa + t + i * NTHREADS);
        d += 1024 * 16;
#pragma unroll
        for (int i = 0; i < 4; i++)
            cp_async16(d + (t + i * NTHREADS) * 16, sb + t + i * NTHREADS);
        asm volatile("cp.async.commit_group;" ::: "memory");
    };

    load_stage(0, 0);
    load_stage(1, 1);
    load_stage(2, 2);

#pragma unroll 1
    for (int it = 0; it < niter; ++it) {
        if (it < niter - 2)
            asm volatile("cp.async.wait_group 2;" ::: "memory");
        else if (it == niter - 2)
            asm volatile("cp.async.wait_group 1;" ::: "memory");
        else
            asm volatile("cp.async.wait_group 0;" ::: "memory");
        __syncthreads();

        if (it + 3 < niter) load_stage(it + 3, (it + 3) % STAGES);

        const uint32_t aS = sbase + (uint32_t)((it % STAGES) * STAGE_CHUNKS * 16);
        const uint32_t bS = aS + 1024 * 16;

#pragma unroll
        for (int ks = 0; ks < 4; ks++) {
            uint32_t a[4][4], b[2][4];
#pragma unroll
            for (int mf = 0; mf < 4; mf++)
                ldmx4(a[mf], aS + arow_off + mf * 2048 + sw[ks]);
#pragma unroll
            for (int p = 0; p < 2; p++)
                ldmx4(b[p], bS + brow_off + p * 2048 + sw[ks]);

#pragma unroll
            for (int mf = 0; mf < 4; mf++)
#pragma unroll
                for (int p = 0; p < 2; p++) {
                    mma_f16(acc[mf][2 * p],     a[mf], b[p][0], b[p][2]);
                    mma_f16(acc[mf][2 * p + 1], a[mf], b[p][1], b[p][3]);
                }
        }
    }

    const int m0 = mt * 128 + wm * 64;
    const int n0 = nt * 256 + wn * 32;

    if (!ATOMIC) {
        float2 bb[4];
#pragma unroll
        for (int nf = 0; nf < 4; nf++)
            bb[nf] = *(const float2*)(bias + n0 + nf * 8 + l4 * 2);
#pragma unroll
        for (int mf = 0; mf < 4; mf++) {
            const int m = m0 + mf * 16 + g4;
            float* r0 = out + (size_t)m * OUT_F;
            float* r1 = out + (size_t)(m + 8) * OUT_F;
#pragma unroll
            for (int nf = 0; nf < 4; nf++) {
                const int n = n0 + nf * 8 + l4 * 2;
                float2 v0, v1;
                v0.x = acc[mf][nf][0] + bb[nf].x;
                v0.y = acc[mf][nf][1] + bb[nf].y;
                v1.x = acc[mf][nf][2] + bb[nf].x;
                v1.y = acc[mf][nf][3] + bb[nf].y;
                *(float2*)(r0 + n) = v0;
                *(float2*)(r1 + n) = v1;
            }
        }
    } else {
#pragma unroll
        for (int mf = 0; mf < 4; mf++) {
            const int m = m0 + mf * 16 + g4;
            float* r0 = out + (size_t)m * OUT_F;
            float* r1 = out + (size_t)(m + 8) * OUT_F;
#pragma unroll
            for (int nf = 0; nf < 4; nf++) {
                const int n = n0 + nf * 8 + l4 * 2;
                atomicAdd(r0 + n,     acc[mf][nf][0]);
                atomicAdd(r0 + n + 1, acc[mf][nf][1]);
                atomicAdd(r1 + n,     acc[mf][nf][2]);
                atomicAdd(r1 + n + 1, acc[mf][nf][3]);
            }
        }
    }
}

// Single GEMM launch: blocks 0..147 full tiles (wave 1), 148..579 quarters.
__global__ __launch_bounds__(NTHREADS, 1)
void gemm_kernel(const float* __restrict__ bias, float* __restrict__ out)
{
    extern __shared__ uint4 smem[];
    const int c = blockIdx.x;
    if (c < 148) {
        gemm_tile<false>(smem, bias, out, c & 15, c >> 4, 0, 64);
    } else {
        const int q    = c - 148;               // 0..431
        const int tile = 148 + (q >> 2);        // 148..255
        const int ks   = q & 3;
        gemm_tile<true>(smem, nullptr, out, tile & 15, tile >> 4, ks * 16, 16);
    }
}

// ---------------------------------------------------------------------------
// Launch: x, qweight, scales, bias, lora_A, lora_B
// ---------------------------------------------------------------------------
extern "C" void kernel_launch(void* const* d_in, const int* in_sizes, int n_in,
                              void* d_out, int out_size)
{
    const float* x      = (const float*)d_in[0];
    const int*   qw     = (const int*)  d_in[1];
    const float* scales = (const float*)d_in[2];
    const float* bias   = (const float*)d_in[3];
    const float* lora_A = (const float*)d_in[4];
    const float* lora_B = (const float*)d_in[5];
    float*       out    = (float*)d_out;
    (void)in_sizes; (void)n_in; (void)out_size;

    cudaFuncSetAttribute(gemm_kernel,
                         cudaFuncAttributeMaxDynamicSharedMemorySize, SMEM_BYTES);

    prep_kernel<<<2156, 512>>>(x, qw, scales, lora_A, lora_B, bias, out);
    gemm_kernel<<<580, NTHREADS, SMEM_BYTES>>>(bias, out);
}

// round 16
// speedup vs baseline: 1.0952x; 1.0058x over previous
#include <cuda_runtime.h>
#include <cuda_fp16.h>
#include <cstdint>

// ---------------------------------------------------------------------------
// BaseLoftqLinear:
//   W' = dequant4(q, s) + 2.0 * (B @ A);   out = x @ W'^T + bias
// fp16 mma.sync.m16n8k16 (fp32 accum), pre-packed/pre-swizzled operands.
// GEMM: one launch, blocks 0..147 = full tiles (exact wave 1, direct store),
// blocks 148..579 = K-quarter tiles of output tiles 148..255 (atomicAdd onto
// bias-pre-initialized region). B fragments software-pipelined one k16 ahead.
// Prep: 512-thread blocks, bias-init first, W/X interleaved.
// ---------------------------------------------------------------------------

#define OUT_F 4096
#define IN_F  4096
#define M_TOK 2048
#define R_LORA 16

// packed 16B-chunk layouts (chunk stored at ch ^ (row&7)):
//   X: [mt(16)][kt(64)][row(128)][chunk(8)]
//   W: [nt(16)][kt(64)][row(256)][chunk(8)]
__device__ uint4 g_Xp[(size_t)M_TOK * IN_F / 8];   // 16 MB
__device__ uint4 g_Wp[(size_t)OUT_F * IN_F / 8];   // 32 MB

#define NTHREADS 512
#define STAGES 4
#define STAGE_CHUNKS 3072                           // A 1024 + B 2048 (16B each)
#define SMEM_BYTES (STAGES * STAGE_CHUNKS * 16)     // 196608

__device__ __forceinline__ uint32_t smem_u32(const void* p) {
    uint32_t a;
    asm("{ .reg .u64 t; cvta.to.shared.u64 t, %1; cvt.u32.u64 %0, t; }"
        : "=r"(a) : "l"(p));
    return a;
}

__device__ __forceinline__ uint32_t h2_u32(__half2 h) {
    union { __half2 h; uint32_t u; } cvt;
    cvt.h = h;
    return cvt.u;
}

__device__ __forceinline__ void cp_async16(uint32_t dst, const void* src) {
    asm volatile("cp.async.cg.shared.global [%0], [%1], 16;"
                 :: "r"(dst), "l"(src) : "memory");
}

__device__ __forceinline__ void ldmx4(uint32_t* r, uint32_t addr) {
    asm volatile("ldmatrix.sync.aligned.m8n8.x4.shared.b16 {%0,%1,%2,%3}, [%4];"
                 : "=r"(r[0]), "=r"(r[1]), "=r"(r[2]), "=r"(r[3]) : "r"(addr));
}

__device__ __forceinline__ void mma_f16(float* d, const uint32_t* a,
                                        uint32_t b0, uint32_t b1) {
    asm volatile(
        "mma.sync.aligned.m16n8k16.row.col.f32.f16.f16.f32 "
        "{%0,%1,%2,%3}, {%4,%5,%6,%7}, {%8,%9}, {%0,%1,%2,%3};"
        : "+f"(d[0]), "+f"(d[1]), "+f"(d[2]), "+f"(d[3])
        : "r"(a[0]), "r"(a[1]), "r"(a[2]), "r"(a[3]), "r"(b0), "r"(b1));
}

// ---------------------------------------------------------------------------
// Prep kernel (512 threads/block):
//   blocks 0..107            : bias init for output tiles 148..255
//   blocks 108..2155, even   : W tile (ib>>1)
//   blocks 108..2155, odd    : X tile (ib>>1)
// ---------------------------------------------------------------------------
__global__ __launch_bounds__(512)
void prep_kernel(const float* __restrict__ x,
                 const int* __restrict__ qweight,
                 const float* __restrict__ scales,
                 const float* __restrict__ lora_A,   // [R, IN_F]
                 const float* __restrict__ lora_B,   // [OUT_F, R]
                 const float* __restrict__ bias,
                 float* __restrict__ out)
{
    const int t = threadIdx.x;
    const int b = blockIdx.x;

    if (b < 108) {
        // ---- bias init for output tile 148 + b ----
        const int tile = 148 + b;               // 148..255
        const int mt = tile & 15;
        const int nt = tile >> 4;
        const int m0 = mt * 128;
        const int n0 = nt * 256;
        const int c4 = t & 63;
        const int rg = t >> 6;                  // 0..7 (16 rows each)
        float4 bv = ((const float4*)(bias + n0))[c4];
        float4* base = (float4*)(out + (size_t)(m0 + rg * 16) * OUT_F + n0) + c4;
#pragma unroll
        for (int r = 0; r < 16; r++)
            base[(size_t)r * (OUT_F / 4)] = bv;
        return;
    }

    const int ib   = b - 108;                   // 0..2047
    const int item = ib >> 1;                   // 0..1023

    if ((ib & 1) == 0) {
        // ---- W tile: nt = item>>6, kt = item&63; 256 rows x 64 cols ----
        __shared__ __half2 sA2[R_LORA][32];
        const int nt = item >> 6;
        const int kt = item & 63;

        if (t < 256) {
            int r  = t >> 4;
            int c4 = t & 15;
            float4 a = *(const float4*)(lora_A + (size_t)r * IN_F + kt * 64 + c4 * 4);
            sA2[r][c4 * 2]     = __floats2half2_rn(a.x, a.y);
            sA2[r][c4 * 2 + 1] = __floats2half2_rn(a.z, a.w);
        }
        __syncthreads();

        const int row   = t >> 1;               // 0..255
        const int hlf   = t & 1;
        const int row_g = nt * 256 + row;

        __half2 Bh[R_LORA];
        {
            float4 b0 = *(const float4*)(lora_B + (size_t)row_g * R_LORA + 0);
            float4 b1 = *(const float4*)(lora_B + (size_t)row_g * R_LORA + 4);
            float4 b2 = *(const float4*)(lora_B + (size_t)row_g * R_LORA + 8);
            float4 b3 = *(const float4*)(lora_B + (size_t)row_g * R_LORA + 12);
            Bh[0]  = __float2half2_rn(2.0f * b0.x);
            Bh[1]  = __float2half2_rn(2.0f * b0.y);
            Bh[2]  = __float2half2_rn(2.0f * b0.z);
            Bh[3]  = __float2half2_rn(2.0f * b0.w);
            Bh[4]  = __float2half2_rn(2.0f * b1.x);
            Bh[5]  = __float2half2_rn(2.0f * b1.y);
            Bh[6]  = __float2half2_rn(2.0f * b1.z);
            Bh[7]  = __float2half2_rn(2.0f * b1.w);
            Bh[8]  = __float2half2_rn(2.0f * b2.x);
            Bh[9]  = __float2half2_rn(2.0f * b2.y);
            Bh[10] = __float2half2_rn(2.0f * b2.z);
            Bh[11] = __float2half2_rn(2.0f * b2.w);
            Bh[12] = __float2half2_rn(2.0f * b3.x);
            Bh[13] = __float2half2_rn(2.0f * b3.y);
            Bh[14] = __float2half2_rn(2.0f * b3.z);
            Bh[15] = __float2half2_rn(2.0f * b3.w);
        }
        const float s = scales[(size_t)row_g * 64 + kt];
        const float step = 2.0f / 15.0f;
        const uint4* qv = (const uint4*)qweight;
        uint4* dst = g_Wp + (size_t)item * 2048 + row * 8;

#pragma unroll
        for (int j = 0; j < 4; j++) {
            const int ch = hlf * 4 + j;
            __half2 l2[4];
            l2[0] = __float2half2_rn(0.0f);
            l2[1] = l2[0]; l2[2] = l2[0]; l2[3] = l2[0];
#pragma unroll
            for (int r = 0; r < R_LORA; r++) {
                uint4 av = *(const uint4*)&sA2[r][ch * 4];
                l2[0] = __hfma2(Bh[r], *(__half2*)&av.x, l2[0]);
                l2[1] = __hfma2(Bh[r], *(__half2*)&av.y, l2[1]);
                l2[2] = __hfma2(Bh[r], *(__half2*)&av.z, l2[2]);
                l2[3] = __hfma2(Bh[r], *(__half2*)&av.w, l2[3]);
            }
            float2 lf0 = __half22float2(l2[0]);
            float2 lf1 = __half22float2(l2[1]);
            float2 lf2 = __half22float2(l2[2]);
            float2 lf3 = __half22float2(l2[3]);

            uint4 q = qv[(size_t)row_g * 512 + kt * 8 + ch];
            float w[8];
            w[0] = fmaf(fmaf((float)(q.x & 15),        step, -1.0f), s, lf0.x);
            w[1] = fmaf(fmaf((float)((q.x >> 4) & 15), step, -1.0f), s, lf0.y);
            w[2] = fmaf(fmaf((float)(q.y & 15),        step, -1.0f), s, lf1.x);
            w[3] = fmaf(fmaf((float)((q.y >> 4) & 15), step, -1.0f), s, lf1.y);
            w[4] = fmaf(fmaf((float)(q.z & 15),        step, -1.0f), s, lf2.x);
            w[5] = fmaf(fmaf((float)((q.z >> 4) & 15), step, -1.0f), s, lf2.y);
            w[6] = fmaf(fmaf((float)(q.w & 15),        step, -1.0f), s, lf3.x);
            w[7] = fmaf(fmaf((float)((q.w >> 4) & 15), step, -1.0f), s, lf3.y);

            uint4 o;
            o.x = h2_u32(__floats2half2_rn(w[0], w[1]));
            o.y = h2_u32(__floats2half2_rn(w[2], w[3]));
            o.z = h2_u32(__floats2half2_rn(w[4], w[5]));
            o.w = h2_u32(__floats2half2_rn(w[6], w[7]));
            dst[ch ^ (row & 7)] = o;
        }
    } else {
        // ---- X tile: 128 rows x 64 cols ----
        const int mt = item >> 6;
        const int kt = item & 63;
        uint4* dst = g_Xp + (size_t)item * 1024;
#pragma unroll
        for (int i = 0; i < 2; i++) {
            int c   = t + i * 512;
            int row = c >> 3;
            int ch  = c & 7;
            const float* src = x + ((size_t)(mt * 128 + row)) * IN_F + kt * 64 + ch * 8;
            float4 v0 = *(const float4*)(src);
            float4 v1 = *(const float4*)(src + 4);
            uint4 o;
            o.x = h2_u32(__floats2half2_rn(v0.x, v0.y));
            o.y = h2_u32(__floats2half2_rn(v0.z, v0.w));
            o.z = h2_u32(__floats2half2_rn(v1.x, v1.y));
            o.w = h2_u32(__floats2half2_rn(v1.z, v1.w));
            dst[row * 8 + (ch ^ (row & 7))] = o;
        }
    }
}

// ---------------------------------------------------------------------------
// GEMM tile body. CTA tile 128x256, BK=64, 4-stage cp.async, 16 warps (2Mx8N).
// B fragments software-pipelined one k16-step ahead.
// ---------------------------------------------------------------------------
template <bool ATOMIC>
__device__ __forceinline__ void gemm_tile(uint4* smem,
                                          const float* __restrict__ bias,
                                          float* __restrict__ out,
                                          int mt, int nt, int it0, int niter)
{
    const uint32_t sbase = smem_u32(smem);
    const int t    = threadIdx.x;
    const int lane = t & 31;
    const int wid  = t >> 5;
    const int g4   = lane >> 2;
    const int l4   = lane & 3;
    const int wm   = wid & 1;
    const int wn   = wid >> 1;

    const int ar = lane & 7;
    const int ag = lane >> 3;
    const int rg = ag & 1;
    const int cg = ag >> 1;
    const uint32_t arow_off = (uint32_t)(wm * 64 + rg * 8 + ar) * 128u;
    const uint32_t brow_off = (uint32_t)(wn * 32 + rg * 8 + ar) * 128u;
    uint32_t sw[4];
#pragma unroll
    for (int ks = 0; ks < 4; ks++)
        sw[ks] = (uint32_t)(((ks * 2 + cg) ^ ar) * 16);

    const uint4* srcA0 = g_Xp + (size_t)mt * 64 * 1024 + (size_t)it0 * 1024;
    const uint4* srcB0 = g_Wp + (size_t)nt * 64 * 2048 + (size_t)it0 * 2048;

    float acc[4][4][4];
#pragma unroll
    for (int mf = 0; mf < 4; mf++)
#pragma unroll
        for (int nf = 0; nf < 4; nf++)
#pragma unroll
            for (int j = 0; j < 4; j++) acc[mf][nf][j] = 0.0f;

    auto load_stage = [&](int it, int s) {
        uint32_t d = sbase + (uint32_t)(s * STAGE_CHUNKS * 16);
        const uint4* sa = srcA0 + (size_t)it * 1024;
        const uint4* sb = srcB0 + (size_t)it * 2048;
#pragma unroll
        for (int i = 0; i < 2; i++)
            cp_async16(d + (t + i * NTHREADS) * 16, sa + t + i * NTHREADS);
        d += 1024 * 16;
#pragma unroll
        for (int i = 0; i < 4; i++)
            cp_async16(d + (t + i * NTHREADS) * 16, sb + t + i * NTHREADS);
        asm volatile("cp.async.commit_group;" ::: "memory");
    };

    load_stage(0, 0);
    load_stage(1, 1);
    load_stage(2, 2);

#pragma unroll 1
    for (int it = 0; it < niter; ++it) {
        if (it < niter - 2)
            asm volatile("cp.async.wait_group 2;" ::: "memory");
        else if (it == niter - 2)
            asm volatile("cp.async.wait_group 1;" ::: "memory");
        else
            asm volatile("cp.async.wait_group 0;" ::: "memory");
        __syncthreads();

        if (it + 3 < niter) load_stage(it + 3, (it + 3) % STAGES);

        const uint32_t aS = sbase + (uint32_t)((it % STAGES) * STAGE_CHUNKS * 16);
        const uint32_t bS = aS + 1024 * 16;
        const uint32_t aBase = aS + arow_off;
        const uint32_t bBase = bS + brow_off;

        // prime B fragments for ks = 0
        uint32_t b0[4], b1[4];
        ldmx4(b0, bBase + sw[0]);
        ldmx4(b1, bBase + 2048 + sw[0]);

#pragma unroll
        for (int ks = 0; ks < 4; ks++) {
            uint32_t a[4][4];
#pragma unroll
            for (int mf = 0; mf < 4; mf++)
                ldmx4(a[mf], aBase + mf * 2048 + sw[ks]);

            // prefetch next ks B fragments before consuming current ones
            uint32_t n0[4], n1[4];
            if (ks < 3) {
                ldmx4(n0, bBase + sw[ks + 1]);
                ldmx4(n1, bBase + 2048 + sw[ks + 1]);
            }

#pragma unroll
            for (int mf = 0; mf < 4; mf++) {
                mma_f16(acc[mf][0], a[mf], b0[0], b0[2]);
                mma_f16(acc[mf][1], a[mf], b0[1], b0[3]);
                mma_f16(acc[mf][2], a[mf], b1[0], b1[2]);
                mma_f16(acc[mf][3], a[mf], b1[1], b1[3]);
            }

            if (ks < 3) {
#pragma unroll
                for (int i = 0; i < 4; i++) { b0[i] = n0[i]; b1[i] = n1[i]; }
            }
        }
    }

    const int m0 = mt * 128 + wm * 64;
    const int n0 = nt * 256 + wn * 32;

    if (!ATOMIC) {
        float2 bb[4];
#pragma unroll
        for (int nf = 0; nf < 4; nf++)
            bb[nf] = *(const float2*)(bias + n0 + nf * 8 + l4 * 2);
#pragma unroll
        for (int mf = 0; mf < 4; mf++) {
            const int m = m0 + mf * 16 + g4;
            float* r0 = out + (size_t)m * OUT_F;
            float* r1 = out + (size_t)(m + 8) * OUT_F;
#pragma unroll
            for (int nf = 0; nf < 4; nf++) {
                const int n = n0 + nf * 8 + l4 * 2;
                float2 v0, v1;
                v0.x = acc[mf][nf][0] + bb[nf].x;
                v0.y = acc[mf][nf][1] + bb[nf].y;
                v1.x = acc[mf][nf][2] + bb[nf].x;
                v1.y = acc[mf][nf][3] + bb[nf].y;
                *(float2*)(r0 + n) = v0;
                *(float2*)(r1 + n) = v1;
            }
        }
    } else {
#pragma unroll
        for (int mf = 0; mf < 4; mf++) {
            const int m = m0 + mf * 16 + g4;
            float* r0 = out + (size_t)m * OUT_F;
            float* r1 = out + (size_t)(m + 8) * OUT_F;
#pragma unroll
            for (int nf = 0; nf < 4; nf++) {
                const int n = n0 + nf * 8 + l4 * 2;
                atomicAdd(r0 + n,     acc[mf][nf][0]);
                atomicAdd(r0 + n + 1, acc[mf][nf][1]);
                atomicAdd(r1 + n,     acc[mf][nf][2]);
                atomicAdd(r1 + n + 1, acc[mf][nf][3]);
            }
        }
    }
}

// Single GEMM launch: blocks 0..147 full tiles (wave 1), 148..579 quarters.
__global__ __launch_bounds__(NTHREADS, 1)
void gemm_kernel(const float* __restrict__ bias, float* __restrict__ out)
{
    extern __shared__ uint4 smem[];
    const int c = blockIdx.x;
    if (c < 148) {
        gemm_tile<false>(smem, bias, out, c & 15, c >> 4, 0, 64);
    } else {
        const int q    = c - 148;               // 0..431
        const int tile = 148 + (q >> 2);        // 148..255
        const int ks   = q & 3;
        gemm_tile<true>(smem, nullptr, out, tile & 15, tile >> 4, ks * 16, 16);
    }
}

// ---------------------------------------------------------------------------
// Launch: x, qweight, scales, bias, lora_A, lora_B
// ---------------------------------------------------------------------------
extern "C" void kernel_launch(void* const* d_in, const int* in_sizes, int n_in,
                              void* d_out, int out_size)
{
    const float* x      = (const float*)d_in[0];
    const int*   qw     = (const int*)  d_in[1];
    const float* scales = (const float*)d_in[2];
    const float* bias   = (const float*)d_in[3];
    const float* lora_A = (const float*)d_in[4];
    const float* lora_B = (const float*)d_in[5];
    float*       out    = (float*)d_out;
    (void)in_sizes; (void)n_in; (void)out_size;

    cudaFuncSetAttribute(gemm_kernel,
                         cudaFuncAttributeMaxDynamicSharedMemorySize, SMEM_BYTES);

    prep_kernel<<<2156, 512>>>(x, qw, scales, lora_A, lora_B, bias, out);
    gemm_kernel<<<580, NTHREADS, SMEM_BYTES>>>(bias, out);
}

// round 17
// speedup vs baseline: 1.1094x; 1.0130x over previous
#include <cuda_runtime.h>
#include <cuda_fp16.h>
#include <cstdint>

// ---------------------------------------------------------------------------
// BaseLoftqLinear:
//   W' = dequant4(q, s) + 2.0 * (B @ A);   out = x @ W'^T + bias
// fp16 mma.sync.m16n8k16 (fp32 accum), pre-packed/pre-swizzled operands.
// GEMM: one launch, blocks 0..147 = full tiles (exact wave 1, direct store),
// blocks 148..579 = K-quarter tiles of output tiles 148..255, accumulated
// with vectorized red.global.add.v2.f32 onto the bias-pre-initialized region.
// Prep: 512-thread blocks, bias-init first, W/X interleaved.
// ---------------------------------------------------------------------------

#define OUT_F 4096
#define IN_F  4096
#define M_TOK 2048
#define R_LORA 16

// packed 16B-chunk layouts (chunk stored at ch ^ (row&7)):
//   X: [mt(16)][kt(64)][row(128)][chunk(8)]
//   W: [nt(16)][kt(64)][row(256)][chunk(8)]
__device__ uint4 g_Xp[(size_t)M_TOK * IN_F / 8];   // 16 MB
__device__ uint4 g_Wp[(size_t)OUT_F * IN_F / 8];   // 32 MB

#define NTHREADS 512
#define STAGES 4
#define STAGE_CHUNKS 3072                           // A 1024 + B 2048 (16B each)
#define SMEM_BYTES (STAGES * STAGE_CHUNKS * 16)     // 196608

__device__ __forceinline__ uint32_t smem_u32(const void* p) {
    uint32_t a;
    asm("{ .reg .u64 t; cvta.to.shared.u64 t, %1; cvt.u32.u64 %0, t; }"
        : "=r"(a) : "l"(p));
    return a;
}

__device__ __forceinline__ uint32_t h2_u32(__half2 h) {
    union { __half2 h; uint32_t u; } cvt;
    cvt.h = h;
    return cvt.u;
}

__device__ __forceinline__ void cp_async16(uint32_t dst, const void* src) {
    asm volatile("cp.async.cg.shared.global [%0], [%1], 16;"
                 :: "r"(dst), "l"(src) : "memory");
}

__device__ __forceinline__ void ldmx4(uint32_t* r, uint32_t addr) {
    asm volatile("ldmatrix.sync.aligned.m8n8.x4.shared.b16 {%0,%1,%2,%3}, [%4];"
                 : "=r"(r[0]), "=r"(r[1]), "=r"(r[2]), "=r"(r[3]) : "r"(addr));
}

__device__ __forceinline__ void mma_f16(float* d, const uint32_t* a,
                                        uint32_t b0, uint32_t b1) {
    asm volatile(
        "mma.sync.aligned.m16n8k16.row.col.f32.f16.f16.f32 "
        "{%0,%1,%2,%3}, {%4,%5,%6,%7}, {%8,%9}, {%0,%1,%2,%3};"
        : "+f"(d[0]), "+f"(d[1]), "+f"(d[2]), "+f"(d[3])
        : "r"(a[0]), "r"(a[1]), "r"(a[2]), "r"(a[3]), "r"(b0), "r"(b1));
}

// vectorized fp32 reduction (sm_90+, non-'a')
__device__ __forceinline__ void red_add_v2(float* p, float v0, float v1) {
    asm volatile("red.global.add.v2.f32 [%0], {%1, %2};"
                 :: "l"(p), "f"(v0), "f"(v1) : "memory");
}

// ---------------------------------------------------------------------------
// Prep kernel (512 threads/block):
//   blocks 0..107            : bias init for output tiles 148..255
//   blocks 108..2155, even   : W tile (ib>>1)
//   blocks 108..2155, odd    : X tile (ib>>1)
// ---------------------------------------------------------------------------
__global__ __launch_bounds__(512)
void prep_kernel(const float* __restrict__ x,
                 const int* __restrict__ qweight,
                 const float* __restrict__ scales,
                 const float* __restrict__ lora_A,   // [R, IN_F]
                 const float* __restrict__ lora_B,   // [OUT_F, R]
                 const float* __restrict__ bias,
                 float* __restrict__ out)
{
    const int t = threadIdx.x;
    const int b = blockIdx.x;

    if (b < 108) {
        // ---- bias init for output tile 148 + b ----
        const int tile = 148 + b;               // 148..255
        const int mt = tile & 15;
        const int nt = tile >> 4;
        const int m0 = mt * 128;
        const int n0 = nt * 256;
        const int c4 = t & 63;
        const int rg = t >> 6;                  // 0..7 (16 rows each)
        float4 bv = ((const float4*)(bias + n0))[c4];
        float4* base = (float4*)(out + (size_t)(m0 + rg * 16) * OUT_F + n0) + c4;
#pragma unroll
        for (int r = 0; r < 16; r++)
            base[(size_t)r * (OUT_F / 4)] = bv;
        return;
    }

    const int ib   = b - 108;                   // 0..2047
    const int item = ib >> 1;                   // 0..1023

    if ((ib & 1) == 0) {
        // ---- W tile: nt = item>>6, kt = item&63; 256 rows x 64 cols ----
        __shared__ __half2 sA2[R_LORA][32];
        const int nt = item >> 6;
        const int kt = item & 63;

        if (t < 256) {
            int r  = t >> 4;
            int c4 = t & 15;
            float4 a = *(const float4*)(lora_A + (size_t)r * IN_F + kt * 64 + c4 * 4);
            sA2[r][c4 * 2]     = __floats2half2_rn(a.x, a.y);
            sA2[r][c4 * 2 + 1] = __floats2half2_rn(a.z, a.w);
        }
        __syncthreads();

        const int row   = t >> 1;               // 0..255
        const int hlf   = t & 1;
        const int row_g = nt * 256 + row;

        __half2 Bh[R_LORA];
        {
            float4 b0 = *(const float4*)(lora_B + (size_t)row_g * R_LORA + 0);
            float4 b1 = *(const float4*)(lora_B + (size_t)row_g * R_LORA + 4);
            float4 b2 = *(const float4*)(lora_B + (size_t)row_g * R_LORA + 8);
            float4 b3 = *(const float4*)(lora_B + (size_t)row_g * R_LORA + 12);
            Bh[0]  = __float2half2_rn(2.0f * b0.x);
            Bh[1]  = __float2half2_rn(2.0f * b0.y);
            Bh[2]  = __float2half2_rn(2.0f * b0.z);
            Bh[3]  = __float2half2_rn(2.0f * b0.w);
            Bh[4]  = __float2half2_rn(2.0f * b1.x);
            Bh[5]  = __float2half2_rn(2.0f * b1.y);
            Bh[6]  = __float2half2_rn(2.0f * b1.z);
            Bh[7]  = __float2half2_rn(2.0f * b1.w);
            Bh[8]  = __float2half2_rn(2.0f * b2.x);
            Bh[9]  = __float2half2_rn(2.0f * b2.y);
            Bh[10] = __float2half2_rn(2.0f * b2.z);
            Bh[11] = __float2half2_rn(2.0f * b2.w);
            Bh[12] = __float2half2_rn(2.0f * b3.x);
            Bh[13] = __float2half2_rn(2.0f * b3.y);
            Bh[14] = __float2half2_rn(2.0f * b3.z);
            Bh[15] = __float2half2_rn(2.0f * b3.w);
        }
        const float s = scales[(size_t)row_g * 64 + kt];
        const float step = 2.0f / 15.0f;
        const uint4* qv = (const uint4*)qweight;
        uint4* dst = g_Wp + (size_t)item * 2048 + row * 8;

#pragma unroll
        for (int j = 0; j < 4; j++) {
            const int ch = hlf * 4 + j;
            __half2 l2[4];
            l2[0] = __float2half2_rn(0.0f);
            l2[1] = l2[0]; l2[2] = l2[0]; l2[3] = l2[0];
#pragma unroll
            for (int r = 0; r < R_LORA; r++) {
                uint4 av = *(const uint4*)&sA2[r][ch * 4];
                l2[0] = __hfma2(Bh[r], *(__half2*)&av.x, l2[0]);
                l2[1] = __hfma2(Bh[r], *(__half2*)&av.y, l2[1]);
                l2[2] = __hfma2(Bh[r], *(__half2*)&av.z, l2[2]);
                l2[3] = __hfma2(Bh[r], *(__half2*)&av.w, l2[3]);
            }
            float2 lf0 = __half22float2(l2[0]);
            float2 lf1 = __half22float2(l2[1]);
            float2 lf2 = __half22float2(l2[2]);
            float2 lf3 = __half22float2(l2[3]);

            uint4 q = qv[(size_t)row_g * 512 + kt * 8 + ch];
            float w[8];
            w[0] = fmaf(fmaf((float)(q.x & 15),        step, -1.0f), s, lf0.x);
            w[1] = fmaf(fmaf((float)((q.x >> 4) & 15), step, -1.0f), s, lf0.y);
            w[2] = fmaf(fmaf((float)(q.y & 15),        step, -1.0f), s, lf1.x);
            w[3] = fmaf(fmaf((float)((q.y >> 4) & 15), step, -1.0f), s, lf1.y);
            w[4] = fmaf(fmaf((float)(q.z & 15),        step, -1.0f), s, lf2.x);
            w[5] = fmaf(fmaf((float)((q.z >> 4) & 15), step, -1.0f), s, lf2.y);
            w[6] = fmaf(fmaf((float)(q.w & 15),        step, -1.0f), s, lf3.x);
            w[7] = fmaf(fmaf((float)((q.w >> 4) & 15), step, -1.0f), s, lf3.y);

            uint4 o;
            o.x = h2_u32(__floats2half2_rn(w[0], w[1]));
            o.y = h2_u32(__floats2half2_rn(w[2], w[3]));
            o.z = h2_u32(__floats2half2_rn(w[4], w[5]));
            o.w = h2_u32(__floats2half2_rn(w[6], w[7]));
            dst[ch ^ (row & 7)] = o;
        }
    } else {
        // ---- X tile: 128 rows x 64 cols ----
        const int mt = item >> 6;
        const int kt = item & 63;
        uint4* dst = g_Xp + (size_t)item * 1024;
#pragma unroll
        for (int i = 0; i < 2; i++) {
            int c   = t + i * 512;
            int row = c >> 3;
            int ch  = c & 7;
            const float* src = x + ((size_t)(mt * 128 + row)) * IN_F + kt * 64 + ch * 8;
            float4 v0 = *(const float4*)(src);
            float4 v1 = *(const float4*)(src + 4);
            uint4 o;
            o.x = h2_u32(__floats2half2_rn(v0.x, v0.y));
            o.y = h2_u32(__floats2half2_rn(v0.z, v0.w));
            o.z = h2_u32(__floats2half2_rn(v1.x, v1.y));
            o.w = h2_u32(__floats2half2_rn(v1.z, v1.w));
            dst[row * 8 + (ch ^ (row & 7))] = o;
        }
    }
}

// ---------------------------------------------------------------------------
// GEMM tile body. CTA tile 128x256, BK=64, 4-stage cp.async, 16 warps (2Mx8N).
// B fragments software-pipelined one k16-step ahead.
// ---------------------------------------------------------------------------
template <bool ATOMIC>
__device__ __forceinline__ void gemm_tile(uint4* smem,
                                          const float* __restrict__ bias,
                                          float* __restrict__ out,
                                          int mt, int nt, int it0, int niter)
{
    const uint32_t sbase = smem_u32(smem);
    const int t    = threadIdx.x;
    const int lane = t & 31;
    const int wid  = t >> 5;
    const int g4   = lane >> 2;
    const int l4   = lane & 3;
    const int wm   = wid & 1;
    const int wn   = wid >> 1;

    const int ar = lane & 7;
    const int ag = lane >> 3;
    const int rg = ag & 1;
    const int cg = ag >> 1;
    const uint32_t arow_off = (uint32_t)(wm * 64 + rg * 8 + ar) * 128u;
    const uint32_t brow_off = (uint32_t)(wn * 32 + rg * 8 + ar) * 128u;
    uint32_t sw[4];
#pragma unroll
    for (int ks = 0; ks < 4; ks++)
        sw[ks] = (uint32_t)(((ks * 2 + cg) ^ ar) * 16);

    const uint4* srcA0 = g_Xp + (size_t)mt * 64 * 1024 + (size_t)it0 * 1024;
    const uint4* srcB0 = g_Wp + (size_t)nt * 64 * 2048 + (size_t)it0 * 2048;

    float acc[4][4][4];
#pragma unroll
    for (int mf = 0; mf < 4; mf++)
#pragma unroll
        for (int nf = 0; nf < 4; nf++)
#pragma unroll
            for (int j = 0; j < 4; j++) acc[mf][nf][j] = 0.0f;

    auto load_stage = [&](int it, int s) {
        uint32_t d = sbase + (uint32_t)(s * STAGE_CHUNKS * 16);
        const uint4* sa = srcA0 + (size_t)it * 1024;
        const uint4* sb = srcB0 + (size_t)it * 2048;
#pragma unroll
        for (int i = 0; i < 2; i++)
            cp_async16(d + (t + i * NTHREADS) * 16, sa + t + i * NTHREADS);
        d += 1024 * 16;
#pragma unroll
        for (int i = 0; i < 4; i++)
            cp_async16(d + (t + i * NTHREADS) * 16, sb + t + i * NTHREADS);
        asm volatile("cp.async.commit_group;" ::: "memory");
    };

    load_stage(0, 0);
    load_stage(1, 1);
    load_stage(2, 2);

#pragma unroll 1
    for (int it = 0; it < niter; ++it) {
        if (it < niter - 2)
            asm volatile("cp.async.wait_group 2;" ::: "memory");
        else if (it == niter - 2)
            asm volatile("cp.async.wait_group 1;" ::: "memory");
        else
            asm volatile("cp.async.wait_group 0;" ::: "memory");
        __syncthreads();

        if (it + 3 < niter) load_stage(it + 3, (it + 3) % STAGES);

        const uint32_t aS = sbase + (uint32_t)((it % STAGES) * STAGE_CHUNKS * 16);
        const uint32_t bS = aS + 1024 * 16;
        const uint32_t aBase = aS + arow_off;
        const uint32_t bBase = bS + brow_off;

        // prime B fragments for ks = 0
        uint32_t b0[4], b1[4];
        ldmx4(b0, bBase + sw[0]);
        ldmx4(b1, bBase + 2048 + sw[0]);

#pragma unroll
        for (int ks = 0; ks < 4; ks++) {
            uint32_t a[4][4];
#pragma unroll
            for (int mf = 0; mf < 4; mf++)
                ldmx4(a[mf], aBase + mf * 2048 + sw[ks]);

            uint32_t n0[4], n1[4];
            if (ks < 3) {
                ldmx4(n0, bBase + sw[ks + 1]);
                ldmx4(n1, bBase + 2048 + sw[ks + 1]);
            }

#pragma unroll
            for (int mf = 0; mf < 4; mf++) {
                mma_f16(acc[mf][0], a[mf], b0[0], b0[2]);
                mma_f16(acc[mf][1], a[mf], b0[1], b0[3]);
                mma_f16(acc[mf][2], a[mf], b1[0], b1[2]);
                mma_f16(acc[mf][3], a[mf], b1[1], b1[3]);
            }

            if (ks < 3) {
#pragma unroll
                for (int i = 0; i < 4; i++) { b0[i] = n0[i]; b1[i] = n1[i]; }
            }
        }
    }

    const int m0 = mt * 128 + wm * 64;
    const int n0 = nt * 256 + wn * 32;

    if (!ATOMIC) {
        float2 bb[4];
#pragma unroll
        for (int nf = 0; nf < 4; nf++)
            bb[nf] = *(const float2*)(bias + n0 + nf * 8 + l4 * 2);
#pragma unroll
        for (int mf = 0; mf < 4; mf++) {
            const int m = m0 + mf * 16 + g4;
            float* r0 = out + (size_t)m * OUT_F;
            float* r1 = out + (size_t)(m + 8) * OUT_F;
#pragma unroll
            for (int nf = 0; nf < 4; nf++) {
                const int n = n0 + nf * 8 + l4 * 2;
                float2 v0, v1;
                v0.x = acc[mf][nf][0] + bb[nf].x;
                v0.y = acc[mf][nf][1] + bb[nf].y;
                v1.x = acc[mf][nf][2] + bb[nf].x;
                v1.y = acc[mf][nf][3] + bb[nf].y;
                *(float2*)(r0 + n) = v0;
                *(float2*)(r1 + n) = v1;
            }
        }
    } else {
        // vectorized reduction epilogue: half the red instruction count
#pragma unroll
        for (int mf = 0; mf < 4; mf++) {
            const int m = m0 + mf * 16 + g4;
            float* r0 = out + (size_t)m * OUT_F;
            float* r1 = out + (size_t)(m + 8) * OUT_F;
#pragma unroll
            for (int nf = 0; nf < 4; nf++) {
                const int n = n0 + nf * 8 + l4 * 2;
                red_add_v2(r0 + n, acc[mf][nf][0], acc[mf][nf][1]);
                red_add_v2(r1 + n, acc[mf][nf][2], acc[mf][nf][3]);
            }
        }
    }
}

// Single GEMM launch: blocks 0..147 full tiles (wave 1), 148..579 quarters.
__global__ __launch_bounds__(NTHREADS, 1)
void gemm_kernel(const float* __restrict__ bias, float* __restrict__ out)
{
    extern __shared__ uint4 smem[];
    const int c = blockIdx.x;
    if (c < 148) {
        gemm_tile<false>(smem, bias, out, c & 15, c >> 4, 0, 64);
    } else {
        const int q    = c - 148;               // 0..431
        const int tile = 148 + (q >> 2);        // 148..255
        const int ks   = q & 3;
        gemm_tile<true>(smem, nullptr, out, tile & 15, tile >> 4, ks * 16, 16);
    }
}

// ---------------------------------------------------------------------------
// Launch: x, qweight, scales, bias, lora_A, lora_B
// ---------------------------------------------------------------------------
extern "C" void kernel_launch(void* const* d_in, const int* in_sizes, int n_in,
                              void* d_out, int out_size)
{
    const float* x      = (const float*)d_in[0];
    const int*   qw     = (const int*)  d_in[1];
    const float* scales = (const float*)d_in[2];
    const float* bias   = (const float*)d_in[3];
    const float* lora_A = (const float*)d_in[4];
    const float* lora_B = (const float*)d_in[5];
    float*       out    = (float*)d_out;
    (void)in_sizes; (void)n_in; (void)out_size;

    cudaFuncSetAttribute(gemm_kernel,
                         cudaFuncAttributeMaxDynamicSharedMemorySize, SMEM_BYTES);

    prep_kernel<<<2156, 512>>>(x, qw, scales, lora_A, lora_B, bias, out);
    gemm_kernel<<<580, NTHREADS, SMEM_BYTES>>>(bias, out);
}